// round 5
// baseline (speedup 1.0000x reference)
#include <cuda_runtime.h>
#include <cuda_bf16.h>
#include <cstdint>

#define Nn 50000
#define NnPad 50048
#define Ee 600000
#define Gg 512
#define NUM_TILES 391   // ceil(50000/128)

// ============================================================================
// PTX helpers: plain (non-'a') instructions only — ldmatrix / mma.sync / cp.async
// ============================================================================
__device__ __forceinline__ uint32_t smem_to_u32(const void* smem_ptr) {
    uint32_t addr;
    asm("{ .reg .u64 tmp; cvta.to.shared.u64 tmp, %1; cvt.u32.u64 %0, tmp; }"
        : "=r"(addr) : "l"(smem_ptr));
    return addr;
}

#define LDSM_X4(r0, r1, r2, r3, addr) \
    asm volatile("ldmatrix.sync.aligned.m8n8.x4.shared.b16 {%0,%1,%2,%3}, [%4];" \
        : "=r"(r0), "=r"(r1), "=r"(r2), "=r"(r3) : "r"(addr))

#define MMA16816(c, a0, a1, a2, a3, b0, b1) \
    asm volatile("mma.sync.aligned.m16n8k16.row.col.f32.bf16.bf16.f32 " \
        "{%0,%1,%2,%3}, {%4,%5,%6,%7}, {%8,%9}, {%0,%1,%2,%3};" \
        : "+f"((c)[0]), "+f"((c)[1]), "+f"((c)[2]), "+f"((c)[3]) \
        : "r"(a0), "r"(a1), "r"(a2), "r"(a3), "r"(b0), "r"(b1))

#define CP_ASYNC16(dst_u32, src_ptr) \
    asm volatile("cp.async.cg.shared.global [%0], [%1], 16;" \
        :: "r"(dst_u32), "l"(src_ptr) : "memory")
#define CP_COMMIT() asm volatile("cp.async.commit_group;" ::: "memory")
#define CP_WAIT1()  asm volatile("cp.async.wait_group 1;" ::: "memory")
#define CP_WAIT0()  asm volatile("cp.async.wait_group 0;" ::: "memory")

// ============================================================================
// Scratch (device globals: allocation-free)
// ============================================================================
__device__ __align__(16) __nv_bfloat16 d_Ahi[2][(size_t)NnPad * 256];
__device__ __align__(16) __nv_bfloat16 d_Alo[2][(size_t)NnPad * 256];
__device__ __align__(16) __nv_bfloat16 d_Wh[3 * 128 * 256];
__device__ __align__(16) __nv_bfloat16 d_Wl[3 * 128 * 256];
__device__ __align__(16) float d_h[(size_t)NnPad * 128];
__device__ int   d_csr[Ee];
__device__ int   d_rowptr[Nn + 1];
__device__ int   d_cursor[Nn];
__device__ int   d_degi[Nn];
__device__ int   d_gptr[Gg + 1];
__device__ int   d_is64;

// ============================================================================
// index dtype handling (int64 vs int32)
// ============================================================================
__device__ __forceinline__ int load_idx(const void* p, long long i, int is64) {
    if (is64) return (int)((const long long*)p)[i];
    return ((const int*)p)[i];
}

// fused: detect int64-vs-int32 (block 0) + zero degi
__global__ void zero_detect_kernel(const void* __restrict__ ei) {
    if (blockIdx.x == 0 && threadIdx.x == 0) {
        const long long* p = (const long long*)ei;
        int ok = 1;
        for (int i = 0; i < 64; ++i) {
            long long v = p[i];
            if (v < 0 || v >= (long long)Nn) { ok = 0; break; }
        }
        d_is64 = ok;
    }
    int i = blockIdx.x * blockDim.x + threadIdx.x;
    int stride = gridDim.x * blockDim.x;
    for (int j = i; j < Nn; j += stride) d_degi[j] = 0;
}

// fused: degree histogram (paired loads) + gptr binary search (block 0)
__global__ void deg_gptr_kernel(const void* __restrict__ ei,
                                const void* __restrict__ batch) {
    const int is64 = d_is64;
    if (blockIdx.x == 0) {
        #pragma unroll
        for (int gg = 0; gg < 2; ++gg) {
            int g = threadIdx.x + gg * 256;
            int lo = 0, hi = Nn;
            while (lo < hi) {
                int mid = (lo + hi) >> 1;
                int v = load_idx(batch, mid, is64);
                if (v < g) lo = mid + 1; else hi = mid;
            }
            d_gptr[g] = lo;
        }
        if (threadIdx.x == 0) d_gptr[Gg] = Nn;
    }
    int gid = blockIdx.x * blockDim.x + threadIdx.x;
    int stride = gridDim.x * blockDim.x;
    if (is64) {
        const long long* p = (const long long*)ei + Ee;
        for (int e = gid * 2; e < Ee; e += stride * 2) {
            longlong2 v = *reinterpret_cast<const longlong2*>(p + e);
            atomicAdd(&d_degi[(int)v.x], 1);
            atomicAdd(&d_degi[(int)v.y], 1);
        }
    } else {
        const int* p = (const int*)ei + Ee;
        for (int e = gid * 2; e < Ee; e += stride * 2) {
            int2 v = *reinterpret_cast<const int2*>(p + e);
            atomicAdd(&d_degi[v.x], 1);
            atomicAdd(&d_degi[v.y], 1);
        }
    }
}

// one-block exclusive scan: degi -> rowptr (+ cursor copy)
__global__ void scan_kernel() {
    __shared__ int sh[1024];
    const int SEG = 49;   // 1024*49 = 50176 >= 50001
    int t = threadIdx.x;
    int base = t * SEG;
    int s = 0;
    #pragma unroll 7
    for (int i = 0; i < SEG; ++i) {
        int idx = base + i;
        if (idx < Nn) s += d_degi[idx];
    }
    sh[t] = s;
    __syncthreads();
    for (int off = 1; off < 1024; off <<= 1) {
        int v = (t >= off) ? sh[t - off] : 0;
        __syncthreads();
        sh[t] += v;
        __syncthreads();
    }
    int run = t ? sh[t - 1] : 0;
    #pragma unroll 7
    for (int i = 0; i < SEG; ++i) {
        int idx = base + i;
        if (idx < Nn) { d_rowptr[idx] = run; d_cursor[idx] = run; run += d_degi[idx]; }
        else if (idx == Nn) { d_rowptr[Nn] = run; }
    }
}

__global__ void csr_fill_kernel(const void* __restrict__ ei) {
    const int is64 = d_is64;
    int gid = blockIdx.x * blockDim.x + threadIdx.x;
    int stride = gridDim.x * blockDim.x;
    if (is64) {
        const long long* ps = (const long long*)ei;
        const long long* pd = ps + Ee;
        for (int e = gid * 2; e < Ee; e += stride * 2) {
            longlong2 s = *reinterpret_cast<const longlong2*>(ps + e);
            longlong2 d = *reinterpret_cast<const longlong2*>(pd + e);
            d_csr[atomicAdd(&d_cursor[(int)d.x], 1)] = (int)s.x;
            d_csr[atomicAdd(&d_cursor[(int)d.y], 1)] = (int)s.y;
        }
    } else {
        const int* ps = (const int*)ei;
        const int* pd = ps + Ee;
        for (int e = gid * 2; e < Ee; e += stride * 2) {
            int2 s = *reinterpret_cast<const int2*>(ps + e);
            int2 d = *reinterpret_cast<const int2*>(pd + e);
            d_csr[atomicAdd(&d_cursor[d.x], 1)] = s.x;
            d_csr[atomicAdd(&d_cursor[d.y], 1)] = s.y;
        }
    }
}

// ============================================================================
// bf16 hi/lo split helpers
// ============================================================================
__device__ __forceinline__ void split_pack(float a, float b, uint32_t& hi, uint32_t& lo) {
    __nv_bfloat16 ha = __float2bfloat16_rn(a), hb = __float2bfloat16_rn(b);
    __nv_bfloat162 hv; hv.x = ha; hv.y = hb;
    hi = *reinterpret_cast<uint32_t*>(&hv);
    float la = a - __bfloat162float(ha);
    float lb = b - __bfloat162float(hb);
    __nv_bfloat162 lv = __floats2bfloat162_rn(la, lb);
    lo = *reinterpret_cast<uint32_t*>(&lv);
}

// fused weight prep (blocks 0..383) + x conversion (blocks 384..)
__global__ void prep_kernel(const float* __restrict__ x,
                            const float* W1l, const float* W1r,
                            const float* W2l, const float* W2r,
                            const float* W3l, const float* W3r) {
    if (blockIdx.x < 384) {
        int idx = blockIdx.x * blockDim.x + threadIdx.x;   // over 3*128*256
        int layer = idx / (128 * 256);
        int rem = idx - layer * 128 * 256;
        int o = rem >> 8, k = rem & 255;
        const float* Wl = layer == 0 ? W1l : layer == 1 ? W2l : W3l;
        const float* Wr = layer == 0 ? W1r : layer == 1 ? W2r : W3r;
        float v = (k < 128) ? Wl[o * 128 + k] : Wr[o * 128 + k - 128];
        __nv_bfloat16 hv = __float2bfloat16_rn(v);
        float lvf = v - __bfloat162float(hv);
        d_Wh[idx] = hv;
        d_Wl[idx] = __float2bfloat16_rn(lvf);
    } else {
        int idx = (blockIdx.x - 384) * blockDim.x + threadIdx.x;   // Nn*32
        if (idx >= Nn * 32) return;
        int n = idx >> 5, c4 = idx & 31;
        float4 v = *reinterpret_cast<const float4*>(x + (size_t)n * 128 + c4 * 4);
        uint32_t h0, l0, h1, l1;
        split_pack(v.x, v.y, h0, l0);
        split_pack(v.z, v.w, h1, l1);
        size_t off = (size_t)n * 256 + 128 + c4 * 4;
        uint2 hh; hh.x = h0; hh.y = h1;
        uint2 ll; ll.x = l0; ll.y = l1;
        *reinterpret_cast<uint2*>(&d_Ahi[1][off]) = hh;
        *reinterpret_cast<uint2*>(&d_Alo[1][off]) = ll;
    }
}

// ============================================================================
// mean aggregation: warp per node, 4x unrolled gather (MLP=4)
// ============================================================================
__global__ void agg_kernel(const float* __restrict__ x, int usex, int outsel) {
    const float* __restrict__ src = usex ? x : d_h;
    int warp = (blockIdx.x * blockDim.x + threadIdx.x) >> 5;
    int lane = threadIdx.x & 31;
    if (warp >= Nn) return;
    int beg = d_rowptr[warp];
    int end = d_rowptr[warp + 1];
    float4 acc = make_float4(0.f, 0.f, 0.f, 0.f);
    int e = beg;
    #pragma unroll 1
    for (; e + 4 <= end; e += 4) {
        int s0 = __ldg(&d_csr[e + 0]);
        int s1 = __ldg(&d_csr[e + 1]);
        int s2 = __ldg(&d_csr[e + 2]);
        int s3 = __ldg(&d_csr[e + 3]);
        float4 v0 = *reinterpret_cast<const float4*>(src + (size_t)s0 * 128 + lane * 4);
        float4 v1 = *reinterpret_cast<const float4*>(src + (size_t)s1 * 128 + lane * 4);
        float4 v2 = *reinterpret_cast<const float4*>(src + (size_t)s2 * 128 + lane * 4);
        float4 v3 = *reinterpret_cast<const float4*>(src + (size_t)s3 * 128 + lane * 4);
        acc.x += v0.x + v1.x + v2.x + v3.x;
        acc.y += v0.y + v1.y + v2.y + v3.y;
        acc.z += v0.z + v1.z + v2.z + v3.z;
        acc.w += v0.w + v1.w + v2.w + v3.w;
    }
    #pragma unroll 1
    for (; e < end; ++e) {
        int s = __ldg(&d_csr[e]);
        float4 v = *reinterpret_cast<const float4*>(src + (size_t)s * 128 + lane * 4);
        acc.x += v.x; acc.y += v.y; acc.z += v.z; acc.w += v.w;
    }
    int deg = end - beg;
    float inv = 1.f / (float)(deg > 1 ? deg : 1);
    acc.x *= inv; acc.y *= inv; acc.z *= inv; acc.w *= inv;
    uint32_t h0, l0, h1, l1;
    split_pack(acc.x, acc.y, h0, l0);
    split_pack(acc.z, acc.w, h1, l1);
    size_t off = (size_t)warp * 256 + lane * 4;
    uint2 hh; hh.x = h0; hh.y = h1;
    uint2 ll; ll.x = l0; ll.y = l1;
    __nv_bfloat16* Ah = d_Ahi[outsel];
    __nv_bfloat16* Al = d_Alo[outsel];
    *reinterpret_cast<uint2*>(Ah + off) = hh;
    *reinterpret_cast<uint2*>(Al + off) = ll;
}

// ============================================================================
// Tensor-core GEMM (mma.sync): h = relu?(A[bufsel] @ Wcat[layer]^T + b)
//   Warp tile 32x64: wm = wid&3 (rows), wn = wid>>2 (cols).
//   Per kstep: 2 A + 4*nW B frag loads; 4 MMAs per B frag load.
// SMEM: Whi 64KB | Wlo 64KB | Abuf 2x16KB | bias 512B  = 164352 B
// ============================================================================
#define OFF_WHI  0
#define OFF_WLO  65536
#define OFF_A    131072
#define OFF_BIAS 163840
#define GEMM_SMEM 164352

__device__ __forceinline__ void prefetch_chunk(const __nv_bfloat16* __restrict__ src,
                                               size_t rowBase, int cbase,
                                               uint32_t dst, int tid) {
    #pragma unroll
    for (int j = 0; j < 4; ++j) {
        int u = tid + j * 256;          // 0..1023 16B units
        int r = u >> 3, uu = u & 7;
        const __nv_bfloat16* s = src + (rowBase + r) * 256 + cbase + uu * 8;
        uint32_t d = dst + r * 128 + (((uu ^ (r & 7))) << 4);
        CP_ASYNC16(d, s);
    }
}

__global__ __launch_bounds__(256, 1)
void sage_mma_gemm(int bufsel, int nextsel, int layer,
                   const float* __restrict__ bias, int do_relu, int writeNext)
{
    extern __shared__ char smem[];
    const uint32_t sb = smem_to_u32(smem);
    const int tid = threadIdx.x;
    const int wid = tid >> 5, lane = tid & 31;
    const int wm = wid & 3, wn = wid >> 2;

    const __nv_bfloat16* __restrict__ Ahi = d_Ahi[bufsel];
    const __nv_bfloat16* __restrict__ Alo = d_Alo[bufsel];
    const __nv_bfloat16* __restrict__ WhiG = d_Wh + layer * 32768;
    const __nv_bfloat16* __restrict__ WloG = d_Wl + layer * 32768;
    __nv_bfloat16* __restrict__ NAh = d_Ahi[nextsel];
    __nv_bfloat16* __restrict__ NAl = d_Alo[nextsel];
    float* sbias = reinterpret_cast<float*>(smem + OFF_BIAS);

    // ---- load W (hi+lo) into swizzled SMEM: 4096 16B-units each ----
    #pragma unroll
    for (int m = 0; m < 2; ++m) {
        const __nv_bfloat16* srcW = m ? WloG : WhiG;
        char* dstW = smem + (m ? OFF_WLO : OFF_WHI);
        #pragma unroll 4
        for (int j = 0; j < 16; ++j) {
            int idx = tid + j * 256;     // 0..4095 16B units
            int n = idx >> 5, u = idx & 31;
            float4 v = *reinterpret_cast<const float4*>(srcW + n * 256 + u * 8);
            *reinterpret_cast<float4*>(dstW + n * 512 + ((u ^ (n & 7)) << 4)) = v;
        }
    }
    if (tid < 128) sbias[tid] = bias[tid];
    __syncthreads();

    const uint32_t sA = sb + OFF_A;

    for (int tile = blockIdx.x; tile < NUM_TILES; tile += gridDim.x) {
        const size_t rowBase = (size_t)tile * 128;

        float acc[64];
        #pragma unroll
        for (int i = 0; i < 64; ++i) acc[i] = 0.f;

        // chunk c: matrix = (c&1)?Alo:Ahi, k-base = (c>>1)*64, buf = c&1
        prefetch_chunk(Ahi, rowBase, 0, sA, tid);
        CP_COMMIT();

        #pragma unroll 1
        for (int c = 0; c < 8; ++c) {
            if (c < 7) {
                int cn = c + 1;
                prefetch_chunk((cn & 1) ? Alo : Ahi, rowBase, (cn >> 1) * 64,
                               sA + (cn & 1) * 16384, tid);
                CP_COMMIT();
                CP_WAIT1();
            } else {
                CP_WAIT0();
            }
            __syncthreads();

            const uint32_t abuf = sA + (c & 1) * 16384;
            const int cbase = (c >> 1) * 64;
            const int nW = (c & 1) ? 1 : 2;   // hi chunk hits Whi+Wlo; lo chunk hits Whi

            #pragma unroll
            for (int ks = 0; ks < 4; ++ks) {
                uint32_t aa[2][4];
                #pragma unroll
                for (int mt = 0; mt < 2; ++mt) {
                    int r = wm * 32 + mt * 16 + (lane & 15);
                    int u = ks * 2 + (lane >> 4);
                    uint32_t ad = abuf + r * 128 + (((u ^ (r & 7))) << 4);
                    LDSM_X4(aa[mt][0], aa[mt][1], aa[mt][2], aa[mt][3], ad);
                }
                #pragma unroll
                for (int w2 = 0; w2 < 2; ++w2) {
                    if (w2 >= nW) break;
                    const uint32_t sW = sb + (w2 ? OFF_WLO : OFF_WHI);
                    #pragma unroll
                    for (int bt = 0; bt < 4; ++bt) {
                        int n = wn * 64 + bt * 16 + (lane & 15);
                        int kg = cbase + ks * 16 + ((lane >> 4) << 3);
                        int u = kg >> 3;
                        uint32_t bd = sW + n * 512 + (((u ^ (n & 7))) << 4);
                        uint32_t b0, b1, b2, b3;
                        LDSM_X4(b0, b1, b2, b3, bd);
                        #pragma unroll
                        for (int mt = 0; mt < 2; ++mt) {
                            MMA16816(&acc[(mt * 8 + bt * 2 + 0) * 4],
                                     aa[mt][0], aa[mt][1], aa[mt][2], aa[mt][3], b0, b2);
                            MMA16816(&acc[(mt * 8 + bt * 2 + 1) * 4],
                                     aa[mt][0], aa[mt][1], aa[mt][2], aa[mt][3], b1, b3);
                        }
                    }
                }
            }
            __syncthreads();
        }

        // ---- epilogue: bias + relu, fp32 out + bf16 split for next layer ----
        const int g = lane >> 2, tg = lane & 3;
        #pragma unroll
        for (int mt = 0; mt < 2; ++mt) {
            const int r0 = (int)rowBase + wm * 32 + mt * 16 + g;
            #pragma unroll
            for (int nt = 0; nt < 8; ++nt) {
                int col = wn * 64 + nt * 8 + tg * 2;
                float2 bb = *reinterpret_cast<const float2*>(&sbias[col]);
                int ai = (mt * 8 + nt) * 4;
                float v0 = acc[ai + 0] + bb.x;
                float v1 = acc[ai + 1] + bb.y;
                float v2 = acc[ai + 2] + bb.x;
                float v3 = acc[ai + 3] + bb.y;
                if (do_relu) {
                    v0 = fmaxf(v0, 0.f); v1 = fmaxf(v1, 0.f);
                    v2 = fmaxf(v2, 0.f); v3 = fmaxf(v3, 0.f);
                }
                if (r0 < Nn) {
                    float2 o; o.x = v0; o.y = v1;
                    *reinterpret_cast<float2*>(d_h + (size_t)r0 * 128 + col) = o;
                    if (writeNext) {
                        uint32_t hh, ll;
                        split_pack(v0, v1, hh, ll);
                        size_t off = (size_t)r0 * 256 + 128 + col;
                        *reinterpret_cast<uint32_t*>(NAh + off) = hh;
                        *reinterpret_cast<uint32_t*>(NAl + off) = ll;
                    }
                }
                if (r0 + 8 < Nn) {
                    float2 o; o.x = v2; o.y = v3;
                    *reinterpret_cast<float2*>(d_h + (size_t)(r0 + 8) * 128 + col) = o;
                    if (writeNext) {
                        uint32_t hh, ll;
                        split_pack(v2, v3, hh, ll);
                        size_t off = (size_t)(r0 + 8) * 256 + 128 + col;
                        *reinterpret_cast<uint32_t*>(NAh + off) = hh;
                        *reinterpret_cast<uint32_t*>(NAl + off) = ll;
                    }
                }
            }
        }
        // buf0's last reads (chunk 6) completed before chunk-7's __syncthreads,
        // so next-tile prefetch into buf0 is safe.
    }
}

// ============================================================================
// fused pool (max/mean per graph) + head GEMV, 8 graphs per block
// ============================================================================
__global__ __launch_bounds__(256) void poolhead_kernel(
    const float* __restrict__ Wlin, const float* __restrict__ blin,
    float* __restrict__ out)
{
    __shared__ float P[8][256];     // pooled [max(128) | mean(128)] per graph
    __shared__ float s1[256], s2[256];
    const int tid = threadIdx.x;
    const int c = tid & 127, hf = tid >> 7;
    const int gbase = blockIdx.x * 8;

    #pragma unroll 1
    for (int gi = 0; gi < 8; ++gi) {
        int g = gbase + gi;
        int beg = d_gptr[g], end = d_gptr[g + 1];
        float mx = -3.402823466e38f, sm = 0.f;
        #pragma unroll 1
        for (int r = beg + hf; r < end; r += 2) {
            float v = d_h[(size_t)r * 128 + c];
            mx = fmaxf(mx, v);
            sm += v;
        }
        s1[tid] = mx; s2[tid] = sm;
        __syncthreads();
        if (hf == 0) {
            mx = fmaxf(mx, s1[c + 128]);
            sm += s2[c + 128];
            int cnt = end - beg;
            P[gi][c]       = (cnt > 0) ? mx : 0.f;
            P[gi][128 + c] = sm / (float)(cnt > 1 ? cnt : 1);
        }
        __syncthreads();
    }

    // head: thread o computes out[g][o] for 8 graphs
    const int o = tid;
    float acc[8];
    float bl = blin[o];
    #pragma unroll
    for (int gi = 0; gi < 8; ++gi) acc[gi] = bl;
    const float4* wr = reinterpret_cast<const float4*>(Wlin + o * 256);
    #pragma unroll 4
    for (int k = 0; k < 64; ++k) {
        float4 w = wr[k];
        #pragma unroll
        for (int gi = 0; gi < 8; ++gi) {
            float4 pv = *reinterpret_cast<const float4*>(&P[gi][k * 4]);
            acc[gi] = fmaf(w.x, pv.x, acc[gi]);
            acc[gi] = fmaf(w.y, pv.y, acc[gi]);
            acc[gi] = fmaf(w.z, pv.z, acc[gi]);
            acc[gi] = fmaf(w.w, pv.w, acc[gi]);
        }
    }
    #pragma unroll
    for (int gi = 0; gi < 8; ++gi)
        out[(size_t)(gbase + gi) * 256 + o] = acc[gi];
}

// ============================================================================
// launch
// ============================================================================
extern "C" void kernel_launch(void* const* d_in, const int* in_sizes, int n_in,
                              void* d_out, int out_size)
{
    const float* x     = (const float*)d_in[0];
    const void*  ei    = d_in[1];
    const void*  batch = d_in[2];
    const float* W1l = (const float*)d_in[3];
    const float* b1  = (const float*)d_in[4];
    const float* W1r = (const float*)d_in[5];
    const float* W2l = (const float*)d_in[6];
    const float* b2  = (const float*)d_in[7];
    const float* W2r = (const float*)d_in[8];
    const float* W3l = (const float*)d_in[9];
    const float* b3  = (const float*)d_in[10];
    const float* W3r = (const float*)d_in[11];
    const float* Wlin = (const float*)d_in[12];
    const float* blin = (const float*)d_in[13];
    float* out = (float*)d_out;

    cudaFuncSetAttribute(sage_mma_gemm, cudaFuncAttributeMaxDynamicSharedMemorySize, GEMM_SMEM);

    zero_detect_kernel<<<98, 512>>>(ei);
    deg_gptr_kernel<<<1024, 256>>>(ei, batch);
    scan_kernel<<<1, 1024>>>();
    csr_fill_kernel<<<1024, 256>>>(ei);
    prep_kernel<<<6634, 256>>>(x, W1l, W1r, W2l, W2r, W3l, W3r);

    const int aggBlocks = (Nn * 32 + 255) / 256;   // warp per node

    // layer 1: reads A[1] (agg(x) | x), writes h1 + A[0] cols 128..255
    agg_kernel<<<aggBlocks, 256>>>(x, 1, 1);
    sage_mma_gemm<<<148, 256, GEMM_SMEM>>>(1, 0, 0, b1, 1, 1);
    // layer 2: reads A[0], writes h2 + A[1] cols 128..255
    agg_kernel<<<aggBlocks, 256>>>(nullptr, 0, 0);
    sage_mma_gemm<<<148, 256, GEMM_SMEM>>>(0, 1, 1, b2, 1, 1);
    // layer 3: reads A[1], writes h3 only
    agg_kernel<<<aggBlocks, 256>>>(nullptr, 0, 1);
    sage_mma_gemm<<<148, 256, GEMM_SMEM>>>(1, 0, 2, b3, 0, 0);

    poolhead_kernel<<<Gg / 8, 256>>>(Wlin, blin, out);
}

// round 6
// speedup vs baseline: 1.1610x; 1.1610x over previous
#include <cuda_runtime.h>
#include <cuda_bf16.h>
#include <cstdint>

#define Nn 50000
#define NnPad 50048
#define Ee 600000
#define Gg 512
#define NUM_TILES 391   // ceil(50000/128)

// ============================================================================
// PTX helpers: plain (non-'a') instructions only — ldmatrix / mma.sync / cp.async
// ============================================================================
__device__ __forceinline__ uint32_t smem_to_u32(const void* smem_ptr) {
    uint32_t addr;
    asm("{ .reg .u64 tmp; cvta.to.shared.u64 tmp, %1; cvt.u32.u64 %0, tmp; }"
        : "=r"(addr) : "l"(smem_ptr));
    return addr;
}

#define LDSM_X4(r0, r1, r2, r3, addr) \
    asm volatile("ldmatrix.sync.aligned.m8n8.x4.shared.b16 {%0,%1,%2,%3}, [%4];" \
        : "=r"(r0), "=r"(r1), "=r"(r2), "=r"(r3) : "r"(addr))

#define MMA16816(c, a0, a1, a2, a3, b0, b1) \
    asm volatile("mma.sync.aligned.m16n8k16.row.col.f32.bf16.bf16.f32 " \
        "{%0,%1,%2,%3}, {%4,%5,%6,%7}, {%8,%9}, {%0,%1,%2,%3};" \
        : "+f"((c)[0]), "+f"((c)[1]), "+f"((c)[2]), "+f"((c)[3]) \
        : "r"(a0), "r"(a1), "r"(a2), "r"(a3), "r"(b0), "r"(b1))

#define CP_ASYNC16(dst_u32, src_ptr) \
    asm volatile("cp.async.cg.shared.global [%0], [%1], 16;" \
        :: "r"(dst_u32), "l"(src_ptr) : "memory")
#define CP_COMMIT() asm volatile("cp.async.commit_group;" ::: "memory")
#define CP_WAIT1()  asm volatile("cp.async.wait_group 1;" ::: "memory")
#define CP_WAIT0()  asm volatile("cp.async.wait_group 0;" ::: "memory")

// ============================================================================
// Scratch (device globals: allocation-free)
// ============================================================================
__device__ __align__(16) __nv_bfloat16 d_Ahi[2][(size_t)NnPad * 256];
__device__ __align__(16) __nv_bfloat16 d_Alo[2][(size_t)NnPad * 256];
__device__ __align__(16) __nv_bfloat16 d_Wh[3 * 128 * 256];
__device__ __align__(16) __nv_bfloat16 d_Wl[3 * 128 * 256];
__device__ __align__(16) float d_h[(size_t)NnPad * 128];
__device__ float d_pooled[Gg * 256];
__device__ int   d_csr[Ee];
__device__ int   d_rowptr[Nn + 1];
__device__ int   d_cursor[Nn];
__device__ int   d_degi[Nn];
__device__ int   d_gptr[Gg + 1];
__device__ int   d_is64;

// ============================================================================
// index dtype handling (int64 vs int32)
// ============================================================================
__device__ __forceinline__ int load_idx(const void* p, long long i, int is64) {
    if (is64) return (int)((const long long*)p)[i];
    return ((const int*)p)[i];
}

// fused: detect int64-vs-int32 (block 0) + zero degi
__global__ void zero_detect_kernel(const void* __restrict__ ei) {
    if (blockIdx.x == 0 && threadIdx.x == 0) {
        const long long* p = (const long long*)ei;
        int ok = 1;
        for (int i = 0; i < 64; ++i) {
            long long v = p[i];
            if (v < 0 || v >= (long long)Nn) { ok = 0; break; }
        }
        d_is64 = ok;
    }
    int i = blockIdx.x * blockDim.x + threadIdx.x;
    int stride = gridDim.x * blockDim.x;
    for (int j = i; j < Nn; j += stride) d_degi[j] = 0;
}

// fused: degree histogram (paired loads) + gptr binary search (block 0)
__global__ void deg_gptr_kernel(const void* __restrict__ ei,
                                const void* __restrict__ batch) {
    const int is64 = d_is64;
    if (blockIdx.x == 0) {
        #pragma unroll
        for (int gg = 0; gg < 2; ++gg) {
            int g = threadIdx.x + gg * 256;
            int lo = 0, hi = Nn;
            while (lo < hi) {
                int mid = (lo + hi) >> 1;
                int v = load_idx(batch, mid, is64);
                if (v < g) lo = mid + 1; else hi = mid;
            }
            d_gptr[g] = lo;
        }
        if (threadIdx.x == 0) d_gptr[Gg] = Nn;
    }
    int gid = blockIdx.x * blockDim.x + threadIdx.x;
    int stride = gridDim.x * blockDim.x;
    if (is64) {
        const long long* p = (const long long*)ei + Ee;
        for (int e = gid * 2; e < Ee; e += stride * 2) {
            longlong2 v = *reinterpret_cast<const longlong2*>(p + e);
            atomicAdd(&d_degi[(int)v.x], 1);
            atomicAdd(&d_degi[(int)v.y], 1);
        }
    } else {
        const int* p = (const int*)ei + Ee;
        for (int e = gid * 2; e < Ee; e += stride * 2) {
            int2 v = *reinterpret_cast<const int2*>(p + e);
            atomicAdd(&d_degi[v.x], 1);
            atomicAdd(&d_degi[v.y], 1);
        }
    }
}

// one-block exclusive scan: degi -> rowptr (+ cursor seed)
__global__ void scan_kernel() {
    __shared__ int sh[1024];
    const int SEG = 49;   // 1024*49 = 50176 >= 50001
    int t = threadIdx.x;
    int base = t * SEG;
    int s = 0;
    #pragma unroll 7
    for (int i = 0; i < SEG; ++i) {
        int idx = base + i;
        if (idx < Nn) s += d_degi[idx];
    }
    sh[t] = s;
    __syncthreads();
    for (int off = 1; off < 1024; off <<= 1) {
        int v = (t >= off) ? sh[t - off] : 0;
        __syncthreads();
        sh[t] += v;
        __syncthreads();
    }
    int run = t ? sh[t - 1] : 0;
    #pragma unroll 7
    for (int i = 0; i < SEG; ++i) {
        int idx = base + i;
        if (idx < Nn) { d_rowptr[idx] = run; d_cursor[idx] = run; run += d_degi[idx]; }
        else if (idx == Nn) { d_rowptr[Nn] = run; }
    }
}

__global__ void csr_fill_kernel(const void* __restrict__ ei) {
    const int is64 = d_is64;
    int gid = blockIdx.x * blockDim.x + threadIdx.x;
    int stride = gridDim.x * blockDim.x;
    if (is64) {
        const long long* ps = (const long long*)ei;
        const long long* pd = ps + Ee;
        for (int e = gid * 2; e < Ee; e += stride * 2) {
            longlong2 s = *reinterpret_cast<const longlong2*>(ps + e);
            longlong2 d = *reinterpret_cast<const longlong2*>(pd + e);
            d_csr[atomicAdd(&d_cursor[(int)d.x], 1)] = (int)s.x;
            d_csr[atomicAdd(&d_cursor[(int)d.y], 1)] = (int)s.y;
        }
    } else {
        const int* ps = (const int*)ei;
        const int* pd = ps + Ee;
        for (int e = gid * 2; e < Ee; e += stride * 2) {
            int2 s = *reinterpret_cast<const int2*>(ps + e);
            int2 d = *reinterpret_cast<const int2*>(pd + e);
            d_csr[atomicAdd(&d_cursor[d.x], 1)] = s.x;
            d_csr[atomicAdd(&d_cursor[d.y], 1)] = s.y;
        }
    }
}

// ============================================================================
// bf16 hi/lo split helpers
// ============================================================================
__device__ __forceinline__ void split_pack(float a, float b, uint32_t& hi, uint32_t& lo) {
    __nv_bfloat16 ha = __float2bfloat16_rn(a), hb = __float2bfloat16_rn(b);
    __nv_bfloat162 hv; hv.x = ha; hv.y = hb;
    hi = *reinterpret_cast<uint32_t*>(&hv);
    float la = a - __bfloat162float(ha);
    float lb = b - __bfloat162float(hb);
    __nv_bfloat162 lv = __floats2bfloat162_rn(la, lb);
    lo = *reinterpret_cast<uint32_t*>(&lv);
}

// fused weight prep (blocks 0..383) + x conversion (blocks 384..)
__global__ void prep_kernel(const float* __restrict__ x,
                            const float* W1l, const float* W1r,
                            const float* W2l, const float* W2r,
                            const float* W3l, const float* W3r) {
    if (blockIdx.x < 384) {
        int idx = blockIdx.x * blockDim.x + threadIdx.x;   // over 3*128*256
        int layer = idx / (128 * 256);
        int rem = idx - layer * 128 * 256;
        int o = rem >> 8, k = rem & 255;
        const float* Wl = layer == 0 ? W1l : layer == 1 ? W2l : W3l;
        const float* Wr = layer == 0 ? W1r : layer == 1 ? W2r : W3r;
        float v = (k < 128) ? Wl[o * 128 + k] : Wr[o * 128 + k - 128];
        __nv_bfloat16 hv = __float2bfloat16_rn(v);
        float lvf = v - __bfloat162float(hv);
        d_Wh[idx] = hv;
        d_Wl[idx] = __float2bfloat16_rn(lvf);
    } else {
        int idx = (blockIdx.x - 384) * blockDim.x + threadIdx.x;   // Nn*32
        if (idx >= Nn * 32) return;
        int n = idx >> 5, c4 = idx & 31;
        float4 v = *reinterpret_cast<const float4*>(x + (size_t)n * 128 + c4 * 4);
        uint32_t h0, l0, h1, l1;
        split_pack(v.x, v.y, h0, l0);
        split_pack(v.z, v.w, h1, l1);
        size_t off = (size_t)n * 256 + 128 + c4 * 4;
        uint2 hh; hh.x = h0; hh.y = h1;
        uint2 ll; ll.x = l0; ll.y = l1;
        *reinterpret_cast<uint2*>(&d_Ahi[1][off]) = hh;
        *reinterpret_cast<uint2*>(&d_Alo[1][off]) = ll;
    }
}

// ============================================================================
// mean aggregation: warp per node, 4x unrolled gather (MLP=4)
// ============================================================================
__global__ void agg_kernel(const float* __restrict__ x, int usex, int outsel) {
    const float* __restrict__ src = usex ? x : d_h;
    int warp = (blockIdx.x * blockDim.x + threadIdx.x) >> 5;
    int lane = threadIdx.x & 31;
    if (warp >= Nn) return;
    int beg = d_rowptr[warp];
    int end = d_rowptr[warp + 1];
    float4 acc = make_float4(0.f, 0.f, 0.f, 0.f);
    int e = beg;
    #pragma unroll 1
    for (; e + 4 <= end; e += 4) {
        int s0 = __ldg(&d_csr[e + 0]);
        int s1 = __ldg(&d_csr[e + 1]);
        int s2 = __ldg(&d_csr[e + 2]);
        int s3 = __ldg(&d_csr[e + 3]);
        float4 v0 = *reinterpret_cast<const float4*>(src + (size_t)s0 * 128 + lane * 4);
        float4 v1 = *reinterpret_cast<const float4*>(src + (size_t)s1 * 128 + lane * 4);
        float4 v2 = *reinterpret_cast<const float4*>(src + (size_t)s2 * 128 + lane * 4);
        float4 v3 = *reinterpret_cast<const float4*>(src + (size_t)s3 * 128 + lane * 4);
        acc.x += v0.x + v1.x + v2.x + v3.x;
        acc.y += v0.y + v1.y + v2.y + v3.y;
        acc.z += v0.z + v1.z + v2.z + v3.z;
        acc.w += v0.w + v1.w + v2.w + v3.w;
    }
    #pragma unroll 1
    for (; e < end; ++e) {
        int s = __ldg(&d_csr[e]);
        float4 v = *reinterpret_cast<const float4*>(src + (size_t)s * 128 + lane * 4);
        acc.x += v.x; acc.y += v.y; acc.z += v.z; acc.w += v.w;
    }
    int deg = end - beg;
    float inv = 1.f / (float)(deg > 1 ? deg : 1);
    acc.x *= inv; acc.y *= inv; acc.z *= inv; acc.w *= inv;
    uint32_t h0, l0, h1, l1;
    split_pack(acc.x, acc.y, h0, l0);
    split_pack(acc.z, acc.w, h1, l1);
    size_t off = (size_t)warp * 256 + lane * 4;
    uint2 hh; hh.x = h0; hh.y = h1;
    uint2 ll; ll.x = l0; ll.y = l1;
    __nv_bfloat16* Ah = d_Ahi[outsel];
    __nv_bfloat16* Al = d_Alo[outsel];
    *reinterpret_cast<uint2*>(Ah + off) = hh;
    *reinterpret_cast<uint2*>(Al + off) = ll;
}

// ============================================================================
// Tensor-core GEMM via mma.sync (HMMA) — R4 version (known-good 338us config)
//   Warp tile 16x128.  A streamed in 128x64 chunks via cp.async double buffer.
// SMEM: Whi 64KB | Wlo 64KB | Abuf 2x16KB | bias 512B  = 164352 B
// ============================================================================
#define OFF_WHI  0
#define OFF_WLO  65536
#define OFF_A    131072
#define OFF_BIAS 163840
#define GEMM_SMEM 164352

__device__ __forceinline__ void prefetch_chunk(const __nv_bfloat16* __restrict__ src,
                                               size_t rowBase, int cbase,
                                               uint32_t dst, int tid) {
    #pragma unroll
    for (int j = 0; j < 4; ++j) {
        int u = tid + j * 256;          // 0..1023 16B units
        int r = u >> 3, uu = u & 7;
        const __nv_bfloat16* s = src + (rowBase + r) * 256 + cbase + uu * 8;
        uint32_t d = dst + r * 128 + (((uu ^ (r & 7))) << 4);
        CP_ASYNC16(d, s);
    }
}

__global__ __launch_bounds__(256, 1)
void sage_mma_gemm(int bufsel, int nextsel, int layer,
                   const float* __restrict__ bias, int do_relu, int writeNext)
{
    extern __shared__ char smem[];
    const uint32_t sb = smem_to_u32(smem);
    const int tid = threadIdx.x;
    const int wid = tid >> 5, lane = tid & 31;

    const __nv_bfloat16* __restrict__ Ahi = d_Ahi[bufsel];
    const __nv_bfloat16* __restrict__ Alo = d_Alo[bufsel];
    const __nv_bfloat16* __restrict__ WhiG = d_Wh + layer * 32768;
    const __nv_bfloat16* __restrict__ WloG = d_Wl + layer * 32768;
    __nv_bfloat16* __restrict__ NAh = d_Ahi[nextsel];
    __nv_bfloat16* __restrict__ NAl = d_Alo[nextsel];
    float* sbias = reinterpret_cast<float*>(smem + OFF_BIAS);

    // ---- load W (hi+lo) into swizzled SMEM: 4096 16B-units each ----
    #pragma unroll
    for (int m = 0; m < 2; ++m) {
        const __nv_bfloat16* srcW = m ? WloG : WhiG;
        char* dstW = smem + (m ? OFF_WLO : OFF_WHI);
        #pragma unroll 4
        for (int j = 0; j < 16; ++j) {
            int idx = tid + j * 256;     // 0..4095 16B units
            int n = idx >> 5, u = idx & 31;
            float4 v = *reinterpret_cast<const float4*>(srcW + n * 256 + u * 8);
            *reinterpret_cast<float4*>(dstW + n * 512 + ((u ^ (n & 7)) << 4)) = v;
        }
    }
    if (tid < 128) sbias[tid] = bias[tid];
    __syncthreads();

    const uint32_t sA  = sb + OFF_A;
    const int wrow = wid * 16;

    for (int tile = blockIdx.x; tile < NUM_TILES; tile += gridDim.x) {
        const size_t rowBase = (size_t)tile * 128;

        float acc[64];
        #pragma unroll
        for (int i = 0; i < 64; ++i) acc[i] = 0.f;

        // chunk c: matrix = (c&1)?Alo:Ahi, k-base = (c>>1)*64, buf = c&1
        prefetch_chunk(Ahi, rowBase, 0, sA, tid);
        CP_COMMIT();

        #pragma unroll 1
        for (int c = 0; c < 8; ++c) {
            if (c < 7) {
                int cn = c + 1;
                prefetch_chunk((cn & 1) ? Alo : Ahi, rowBase, (cn >> 1) * 64,
                               sA + (cn & 1) * 16384, tid);
                CP_COMMIT();
                CP_WAIT1();
            } else {
                CP_WAIT0();
            }
            __syncthreads();

            const uint32_t abuf = sA + (c & 1) * 16384;
            const int cbase = (c >> 1) * 64;
            const int nW = (c & 1) ? 1 : 2;   // hi chunk hits Whi+Wlo; lo chunk hits Whi

            #pragma unroll
            for (int ks = 0; ks < 4; ++ks) {
                uint32_t a0, a1, a2, a3;
                {
                    int r = wrow + (lane & 15);
                    int u = ks * 2 + (lane >> 4);
                    uint32_t ad = abuf + r * 128 + (((u ^ (r & 7))) << 4);
                    LDSM_X4(a0, a1, a2, a3, ad);
                }
                #pragma unroll
                for (int w2 = 0; w2 < 2; ++w2) {
                    if (w2 >= nW) break;
                    const uint32_t sW = sb + (w2 ? OFF_WLO : OFF_WHI);
                    #pragma unroll
                    for (int ntp = 0; ntp < 8; ++ntp) {
                        int n = ntp * 16 + (lane & 15);
                        int kg = cbase + ks * 16 + ((lane >> 4) << 3);
                        int u = kg >> 3;
                        uint32_t bd = sW + n * 512 + (((u ^ (n & 7))) << 4);
                        uint32_t b0, b1, b2, b3;
                        LDSM_X4(b0, b1, b2, b3, bd);
                        MMA16816(&acc[(ntp * 2 + 0) * 4], a0, a1, a2, a3, b0, b2);
                        MMA16816(&acc[(ntp * 2 + 1) * 4], a0, a1, a2, a3, b1, b3);
                    }
                }
            }
            __syncthreads();
        }

        // ---- epilogue: bias + relu, fp32 out + bf16 split for next layer ----
        const int g = lane >> 2, tg = lane & 3;
        const int r0g = (int)rowBase + wrow + g;
        #pragma unroll
        for (int nt = 0; nt < 16; ++nt) {
            int col = nt * 8 + tg * 2;
            float2 bb = *reinterpret_cast<const float2*>(&sbias[col]);
            float v0 = acc[nt * 4 + 0] + bb.x;
            float v1 = acc[nt * 4 + 1] + bb.y;
            float v2 = acc[nt * 4 + 2] + bb.x;
            float v3 = acc[nt * 4 + 3] + bb.y;
            if (do_relu) {
                v0 = fmaxf(v0, 0.f); v1 = fmaxf(v1, 0.f);
                v2 = fmaxf(v2, 0.f); v3 = fmaxf(v3, 0.f);
            }
            if (r0g < Nn) {
                float2 o; o.x = v0; o.y = v1;
                *reinterpret_cast<float2*>(d_h + (size_t)r0g * 128 + col) = o;
                if (writeNext) {
                    uint32_t hh, ll;
                    split_pack(v0, v1, hh, ll);
                    size_t off = (size_t)r0g * 256 + 128 + col;
                    *reinterpret_cast<uint32_t*>(NAh + off) = hh;
                    *reinterpret_cast<uint32_t*>(NAl + off) = ll;
                }
            }
            if (r0g + 8 < Nn) {
                float2 o; o.x = v2; o.y = v3;
                *reinterpret_cast<float2*>(d_h + (size_t)(r0g + 8) * 128 + col) = o;
                if (writeNext) {
                    uint32_t hh, ll;
                    split_pack(v2, v3, hh, ll);
                    size_t off = (size_t)(r0g + 8) * 256 + 128 + col;
                    *reinterpret_cast<uint32_t*>(NAh + off) = hh;
                    *reinterpret_cast<uint32_t*>(NAl + off) = ll;
                }
            }
        }
    }
}

// ============================================================================
// pooling: one graph per block, 256 threads (2-way row split halves latency chain)
// ============================================================================
__global__ __launch_bounds__(256) void pool_kernel() {
    __shared__ float s1[256], s2[256];
    int g = blockIdx.x;
    int c = threadIdx.x & 127, hf = threadIdx.x >> 7;
    int beg = d_gptr[g], end = d_gptr[g + 1];
    float mx = -3.402823466e38f, sm = 0.f;
    #pragma unroll 1
    for (int r = beg + hf; r < end; r += 2) {
        float v = d_h[(size_t)r * 128 + c];
        mx = fmaxf(mx, v);
        sm += v;
    }
    s1[threadIdx.x] = mx; s2[threadIdx.x] = sm;
    __syncthreads();
    if (hf == 0) {
        mx = fmaxf(mx, s1[c + 128]);
        sm += s2[c + 128];
        int cnt = end - beg;
        d_pooled[g * 256 + c]       = (cnt > 0) ? mx : 0.f;
        d_pooled[g * 256 + 128 + c] = sm / (float)(cnt > 1 ? cnt : 1);
    }
}

// head: out = pooled @ Wlin^T + blin  (R4 version)
__global__ __launch_bounds__(256) void head_kernel(
    const float* __restrict__ Wlin, const float* __restrict__ blin,
    float* __restrict__ out)
{
    __shared__ float p[256];
    int g = blockIdx.x, o = threadIdx.x;
    p[o] = d_pooled[g * 256 + o];
    __syncthreads();
    float acc = blin[o];
    const float4* wr = reinterpret_cast<const float4*>(Wlin + o * 256);
    #pragma unroll 8
    for (int k = 0; k < 64; ++k) {
        float4 w = wr[k];
        float4 pv = *reinterpret_cast<const float4*>(&p[k * 4]);
        acc = fmaf(w.x, pv.x, acc);
        acc = fmaf(w.y, pv.y, acc);
        acc = fmaf(w.z, pv.z, acc);
        acc = fmaf(w.w, pv.w, acc);
    }
    out[g * 256 + o] = acc;
}

// ============================================================================
// launch
// ============================================================================
extern "C" void kernel_launch(void* const* d_in, const int* in_sizes, int n_in,
                              void* d_out, int out_size)
{
    const float* x     = (const float*)d_in[0];
    const void*  ei    = d_in[1];
    const void*  batch = d_in[2];
    const float* W1l = (const float*)d_in[3];
    const float* b1  = (const float*)d_in[4];
    const float* W1r = (const float*)d_in[5];
    const float* W2l = (const float*)d_in[6];
    const float* b2  = (const float*)d_in[7];
    const float* W2r = (const float*)d_in[8];
    const float* W3l = (const float*)d_in[9];
    const float* b3  = (const float*)d_in[10];
    const float* W3r = (const float*)d_in[11];
    const float* Wlin = (const float*)d_in[12];
    const float* blin = (const float*)d_in[13];
    float* out = (float*)d_out;

    cudaFuncSetAttribute(sage_mma_gemm, cudaFuncAttributeMaxDynamicSharedMemorySize, GEMM_SMEM);

    zero_detect_kernel<<<98, 512>>>(ei);
    deg_gptr_kernel<<<512, 256>>>(ei, batch);
    scan_kernel<<<1, 1024>>>();
    csr_fill_kernel<<<1024, 256>>>(ei);
    prep_kernel<<<6634, 256>>>(x, W1l, W1r, W2l, W2r, W3l, W3r);

    const int aggBlocks = (Nn * 32 + 255) / 256;   // warp per node

    // layer 1: reads A[1] (agg(x) | x), writes h1 + A[0] cols 128..255
    agg_kernel<<<aggBlocks, 256>>>(x, 1, 1);
    sage_mma_gemm<<<148, 256, GEMM_SMEM>>>(1, 0, 0, b1, 1, 1);
    // layer 2: reads A[0], writes h2 + A[1] cols 128..255
    agg_kernel<<<aggBlocks, 256>>>(nullptr, 0, 0);
    sage_mma_gemm<<<148, 256, GEMM_SMEM>>>(0, 1, 1, b2, 1, 1);
    // layer 3: reads A[1], writes h3 only
    agg_kernel<<<aggBlocks, 256>>>(nullptr, 0, 1);
    sage_mma_gemm<<<148, 256, GEMM_SMEM>>>(1, 0, 2, b3, 0, 0);

    pool_kernel<<<Gg, 256>>>();
    head_kernel<<<Gg, 256>>>(Wlin, blin, out);
}

// round 7
// speedup vs baseline: 1.2732x; 1.0967x over previous
#include <cuda_runtime.h>
#include <cuda_bf16.h>
#include <cstdint>

#define Nn 50000
#define NnPad 50048
#define Ee 600000
#define Gg 512
#define NUM_TILES 391   // ceil(50000/128)

// ============================================================================
// PTX helpers: plain (non-'a') instructions only — ldmatrix / mma.sync / cp.async
// ============================================================================
__device__ __forceinline__ uint32_t smem_to_u32(const void* smem_ptr) {
    uint32_t addr;
    asm("{ .reg .u64 tmp; cvta.to.shared.u64 tmp, %1; cvt.u32.u64 %0, tmp; }"
        : "=r"(addr) : "l"(smem_ptr));
    return addr;
}

#define LDSM_X4(r0, r1, r2, r3, addr) \
    asm volatile("ldmatrix.sync.aligned.m8n8.x4.shared.b16 {%0,%1,%2,%3}, [%4];" \
        : "=r"(r0), "=r"(r1), "=r"(r2), "=r"(r3) : "r"(addr))

#define MMA16816(c, a0, a1, a2, a3, b0, b1) \
    asm volatile("mma.sync.aligned.m16n8k16.row.col.f32.bf16.bf16.f32 " \
        "{%0,%1,%2,%3}, {%4,%5,%6,%7}, {%8,%9}, {%0,%1,%2,%3};" \
        : "+f"((c)[0]), "+f"((c)[1]), "+f"((c)[2]), "+f"((c)[3]) \
        : "r"(a0), "r"(a1), "r"(a2), "r"(a3), "r"(b0), "r"(b1))

#define CP_ASYNC16(dst_u32, src_ptr) \
    asm volatile("cp.async.cg.shared.global [%0], [%1], 16;" \
        :: "r"(dst_u32), "l"(src_ptr) : "memory")
#define CP_COMMIT() asm volatile("cp.async.commit_group;" ::: "memory")
#define CP_WAIT1()  asm volatile("cp.async.wait_group 1;" ::: "memory")
#define CP_WAIT0()  asm volatile("cp.async.wait_group 0;" ::: "memory")

// ============================================================================
// Scratch (device globals: allocation-free)
// ============================================================================
__device__ __align__(16) __nv_bfloat16 d_Ahi[2][(size_t)NnPad * 256];
__device__ __align__(16) __nv_bfloat16 d_Alo[2][(size_t)NnPad * 256];
__device__ __align__(16) __nv_bfloat16 d_Wh[3 * 128 * 256];
__device__ __align__(16) __nv_bfloat16 d_Wl[3 * 128 * 256];
__device__ __align__(16) float d_h[(size_t)NnPad * 128];
__device__ float d_pooled[Gg * 256];
__device__ int   d_csr[Ee];
__device__ int   d_rowptr[Nn + 1];
__device__ int   d_cursor[Nn];
__device__ int   d_degi[Nn];
__device__ int   d_gptr[Gg + 1];
__device__ int   d_is64;

// ============================================================================
// index dtype handling (int64 vs int32)  — R4-exact
// ============================================================================
__device__ __forceinline__ int load_idx(const void* p, long long i, int is64) {
    if (is64) return (int)((const long long*)p)[i];
    return ((const int*)p)[i];
}
__global__ void detect_kernel(const void* __restrict__ ei) {
    const long long* p = (const long long*)ei;
    int ok = 1;
    for (int i = 0; i < 64; ++i) {
        long long v = p[i];
        if (v < 0 || v >= (long long)Nn) { ok = 0; break; }
    }
    d_is64 = ok;
}

__global__ void gptr_kernel(const void* __restrict__ batch) {
    int is64 = d_is64;
    int g = threadIdx.x;   // 0..511
    int lo = 0, hi = Nn;
    while (lo < hi) {
        int mid = (lo + hi) >> 1;
        int v = load_idx(batch, mid, is64);
        if (v < g) lo = mid + 1; else hi = mid;
    }
    d_gptr[g] = lo;
    if (g == 0) d_gptr[Gg] = Nn;
}

__global__ void zero_kernel() {
    int i = blockIdx.x * blockDim.x + threadIdx.x;
    int stride = gridDim.x * blockDim.x;
    for (int j = i; j < Nn; j += stride) { d_degi[j] = 0; d_cursor[j] = 0; }
}

__global__ void deg_hist_kernel(const void* __restrict__ ei) {
    int is64 = d_is64;
    int stride = gridDim.x * blockDim.x;
    for (int e = blockIdx.x * blockDim.x + threadIdx.x; e < Ee; e += stride) {
        int dst = load_idx(ei, (long long)Ee + e, is64);
        atomicAdd(&d_degi[dst], 1);
    }
}

// one-block exclusive scan: degi -> rowptr
__global__ void scan_kernel() {
    __shared__ int sh[1024];
    const int SEG = 49;   // 1024*49 = 50176 >= 50001
    int t = threadIdx.x;
    int base = t * SEG;
    int s = 0;
    #pragma unroll 7
    for (int i = 0; i < SEG; ++i) {
        int idx = base + i;
        if (idx < Nn) s += d_degi[idx];
    }
    sh[t] = s;
    __syncthreads();
    for (int off = 1; off < 1024; off <<= 1) {
        int v = (t >= off) ? sh[t - off] : 0;
        __syncthreads();
        sh[t] += v;
        __syncthreads();
    }
    int run = t ? sh[t - 1] : 0;
    #pragma unroll 7
    for (int i = 0; i < SEG; ++i) {
        int idx = base + i;
        if (idx < Nn) { d_rowptr[idx] = run; run += d_degi[idx]; }
        else if (idx == Nn) { d_rowptr[Nn] = run; }
    }
}

__global__ void csr_fill_kernel(const void* __restrict__ ei) {
    int is64 = d_is64;
    int stride = gridDim.x * blockDim.x;
    for (int e = blockIdx.x * blockDim.x + threadIdx.x; e < Ee; e += stride) {
        int src = load_idx(ei, e, is64);
        int dst = load_idx(ei, (long long)Ee + e, is64);
        int pos = d_rowptr[dst] + atomicAdd(&d_cursor[dst], 1);
        d_csr[pos] = src;
    }
}

// ============================================================================
// bf16 hi/lo split helpers
// ============================================================================
__device__ __forceinline__ void split_pack(float a, float b, uint32_t& hi, uint32_t& lo) {
    __nv_bfloat16 ha = __float2bfloat16_rn(a), hb = __float2bfloat16_rn(b);
    __nv_bfloat162 hv; hv.x = ha; hv.y = hb;
    hi = *reinterpret_cast<uint32_t*>(&hv);
    float la = a - __bfloat162float(ha);
    float lb = b - __bfloat162float(hb);
    __nv_bfloat162 lv = __floats2bfloat162_rn(la, lb);
    lo = *reinterpret_cast<uint32_t*>(&lv);
}

// convert weights: Wcat[layer][o][k] = k<128 ? Wl[o][k] : Wr[o][k-128], split hi/lo
__global__ void wprep_kernel(const float* W1l, const float* W1r,
                             const float* W2l, const float* W2r,
                             const float* W3l, const float* W3r) {
    int idx = blockIdx.x * blockDim.x + threadIdx.x;   // over 3*128*256
    if (idx >= 3 * 128 * 256) return;
    int layer = idx / (128 * 256);
    int rem = idx - layer * 128 * 256;
    int o = rem >> 8, k = rem & 255;
    const float* Wl = layer == 0 ? W1l : layer == 1 ? W2l : W3l;
    const float* Wr = layer == 0 ? W1r : layer == 1 ? W2r : W3r;
    float v = (k < 128) ? Wl[o * 128 + k] : Wr[o * 128 + k - 128];
    __nv_bfloat16 hv = __float2bfloat16_rn(v);
    float lvf = v - __bfloat162float(hv);
    d_Wh[idx] = hv;
    d_Wl[idx] = __float2bfloat16_rn(lvf);
}

// convert x into A buf[1], cols 128..255
__global__ void xconv_kernel(const float* __restrict__ x) {
    int idx = blockIdx.x * blockDim.x + threadIdx.x;   // Nn*32
    if (idx >= Nn * 32) return;
    int n = idx >> 5, c4 = idx & 31;
    float4 v = *reinterpret_cast<const float4*>(x + (size_t)n * 128 + c4 * 4);
    uint32_t h0, l0, h1, l1;
    split_pack(v.x, v.y, h0, l0);
    split_pack(v.z, v.w, h1, l1);
    size_t off = (size_t)n * 256 + 128 + c4 * 4;
    uint2 hh; hh.x = h0; hh.y = h1;
    uint2 ll; ll.x = l0; ll.y = l1;
    *reinterpret_cast<uint2*>(&d_Ahi[1][off]) = hh;
    *reinterpret_cast<uint2*>(&d_Alo[1][off]) = ll;
}

// ============================================================================
// mean aggregation: warp per node  — R4-exact (compiler schedules the loop)
// ============================================================================
__global__ void agg_kernel(const float* __restrict__ x, int usex, int outsel) {
    const float* src = usex ? x : d_h;
    int warp = (blockIdx.x * blockDim.x + threadIdx.x) >> 5;
    int lane = threadIdx.x & 31;
    if (warp >= Nn) return;
    int beg = d_rowptr[warp];
    int end = d_rowptr[warp + 1];
    float4 acc = make_float4(0.f, 0.f, 0.f, 0.f);
    for (int e = beg; e < end; ++e) {
        int s = d_csr[e];
        float4 v = *reinterpret_cast<const float4*>(src + (size_t)s * 128 + lane * 4);
        acc.x += v.x; acc.y += v.y; acc.z += v.z; acc.w += v.w;
    }
    int deg = end - beg;
    float inv = 1.f / (float)(deg > 1 ? deg : 1);
    acc.x *= inv; acc.y *= inv; acc.z *= inv; acc.w *= inv;
    uint32_t h0, l0, h1, l1;
    split_pack(acc.x, acc.y, h0, l0);
    split_pack(acc.z, acc.w, h1, l1);
    size_t off = (size_t)warp * 256 + lane * 4;
    uint2 hh; hh.x = h0; hh.y = h1;
    uint2 ll; ll.x = l0; ll.y = l1;
    __nv_bfloat16* Ah = d_Ahi[outsel];
    __nv_bfloat16* Al = d_Alo[outsel];
    *reinterpret_cast<uint2*>(Ah + off) = hh;
    *reinterpret_cast<uint2*>(Al + off) = ll;
}

// ============================================================================
// Tensor-core GEMM via mma.sync — R4 mainloop + SMEM-STAGED epilogue.
//   Epilogue: fragments -> 64-row fp32 stage in SMEM (reusing A-buf region),
//   then coalesced global writes (float4 h rows, uint2 NAh/NAl rows).
// SMEM: Whi 64KB | Wlo 64KB | Abuf/stage 2x16KB | bias 512B  = 164352 B
// ============================================================================
#define OFF_WHI  0
#define OFF_WLO  65536
#define OFF_A    131072
#define OFF_BIAS 163840
#define GEMM_SMEM 164352

__device__ __forceinline__ void prefetch_chunk(const __nv_bfloat16* __restrict__ src,
                                               size_t rowBase, int cbase,
                                               uint32_t dst, int tid) {
    #pragma unroll
    for (int j = 0; j < 4; ++j) {
        int u = tid + j * 256;          // 0..1023 16B units
        int r = u >> 3, uu = u & 7;
        const __nv_bfloat16* s = src + (rowBase + r) * 256 + cbase + uu * 8;
        uint32_t d = dst + r * 128 + (((uu ^ (r & 7))) << 4);
        CP_ASYNC16(d, s);
    }
}

__global__ __launch_bounds__(256, 1)
void sage_mma_gemm(int bufsel, int nextsel, int layer,
                   const float* __restrict__ bias, int do_relu, int writeNext)
{
    extern __shared__ char smem[];
    const uint32_t sb = smem_to_u32(smem);
    const int tid = threadIdx.x;
    const int wid = tid >> 5, lane = tid & 31;

    const __nv_bfloat16* __restrict__ Ahi = d_Ahi[bufsel];
    const __nv_bfloat16* __restrict__ Alo = d_Alo[bufsel];
    const __nv_bfloat16* __restrict__ WhiG = d_Wh + layer * 32768;
    const __nv_bfloat16* __restrict__ WloG = d_Wl + layer * 32768;
    __nv_bfloat16* __restrict__ NAh = d_Ahi[nextsel];
    __nv_bfloat16* __restrict__ NAl = d_Alo[nextsel];
    float* sbias = reinterpret_cast<float*>(smem + OFF_BIAS);

    // ---- load W (hi+lo) into swizzled SMEM: 4096 16B-units each ----
    #pragma unroll
    for (int m = 0; m < 2; ++m) {
        const __nv_bfloat16* srcW = m ? WloG : WhiG;
        char* dstW = smem + (m ? OFF_WLO : OFF_WHI);
        #pragma unroll 4
        for (int j = 0; j < 16; ++j) {
            int idx = tid + j * 256;     // 0..4095 16B units
            int n = idx >> 5, u = idx & 31;
            float4 v = *reinterpret_cast<const float4*>(srcW + n * 256 + u * 8);
            *reinterpret_cast<float4*>(dstW + n * 512 + ((u ^ (n & 7)) << 4)) = v;
        }
    }
    if (tid < 128) sbias[tid] = bias[tid];
    __syncthreads();

    const uint32_t sA  = sb + OFF_A;
    const int wrow = wid * 16;

    for (int tile = blockIdx.x; tile < NUM_TILES; tile += gridDim.x) {
        const size_t rowBase = (size_t)tile * 128;

        float acc[64];
        #pragma unroll
        for (int i = 0; i < 64; ++i) acc[i] = 0.f;

        // chunk c: matrix = (c&1)?Alo:Ahi, k-base = (c>>1)*64, buf = c&1
        prefetch_chunk(Ahi, rowBase, 0, sA, tid);
        CP_COMMIT();

        #pragma unroll 1
        for (int c = 0; c < 8; ++c) {
            if (c < 7) {
                int cn = c + 1;
                prefetch_chunk((cn & 1) ? Alo : Ahi, rowBase, (cn >> 1) * 64,
                               sA + (cn & 1) * 16384, tid);
                CP_COMMIT();
                CP_WAIT1();
            } else {
                CP_WAIT0();
            }
            __syncthreads();

            const uint32_t abuf = sA + (c & 1) * 16384;
            const int cbase = (c >> 1) * 64;
            const int nW = (c & 1) ? 1 : 2;   // hi chunk hits Whi+Wlo; lo chunk hits Whi

            #pragma unroll
            for (int ks = 0; ks < 4; ++ks) {
                uint32_t a0, a1, a2, a3;
                {
                    int r = wrow + (lane & 15);
                    int u = ks * 2 + (lane >> 4);
                    uint32_t ad = abuf + r * 128 + (((u ^ (r & 7))) << 4);
                    LDSM_X4(a0, a1, a2, a3, ad);
                }
                #pragma unroll
                for (int w2 = 0; w2 < 2; ++w2) {
                    if (w2 >= nW) break;
                    const uint32_t sW = sb + (w2 ? OFF_WLO : OFF_WHI);
                    #pragma unroll
                    for (int ntp = 0; ntp < 8; ++ntp) {
                        int n = ntp * 16 + (lane & 15);
                        int kg = cbase + ks * 16 + ((lane >> 4) << 3);
                        int u = kg >> 3;
                        uint32_t bd = sW + n * 512 + (((u ^ (n & 7))) << 4);
                        uint32_t b0, b1, b2, b3;
                        LDSM_X4(b0, b1, b2, b3, bd);
                        MMA16816(&acc[(ntp * 2 + 0) * 4], a0, a1, a2, a3, b0, b2);
                        MMA16816(&acc[(ntp * 2 + 1) * 4], a0, a1, a2, a3, b1, b3);
                    }
                }
            }
            __syncthreads();
        }

        // ---- staged epilogue: two 64-row halves through 32KB SMEM stage ----
        // stage layout: 64 rows x 512B; float2 unit u (0..63) stored at
        //   r*512 + ((u ^ ((r&7)<<2)) << 3)   (XOR swizzle, conflict-light)
        const int g = lane >> 2, tg = lane & 3;
        #pragma unroll 1
        for (int half = 0; half < 2; ++half) {
            if ((wid >> 2) == half) {
                const int lr = (wid & 3) * 16 + g;    // local row 0..63 (and +8)
                #pragma unroll
                for (int nt = 0; nt < 16; ++nt) {
                    int col2 = nt * 8 + tg * 2;
                    float2 bb = *reinterpret_cast<const float2*>(&sbias[col2]);
                    float v0 = acc[nt * 4 + 0] + bb.x;
                    float v1 = acc[nt * 4 + 1] + bb.y;
                    float v2 = acc[nt * 4 + 2] + bb.x;
                    float v3 = acc[nt * 4 + 3] + bb.y;
                    if (do_relu) {
                        v0 = fmaxf(v0, 0.f); v1 = fmaxf(v1, 0.f);
                        v2 = fmaxf(v2, 0.f); v3 = fmaxf(v3, 0.f);
                    }
                    int u = nt * 4 + tg;
                    {
                        int r = lr;
                        float2 t; t.x = v0; t.y = v1;
                        *reinterpret_cast<float2*>(smem + OFF_A + r * 512 +
                            ((u ^ ((r & 7) << 2)) << 3)) = t;
                    }
                    {
                        int r = lr + 8;
                        float2 t; t.x = v2; t.y = v3;
                        *reinterpret_cast<float2*>(smem + OFF_A + r * 512 +
                            ((u ^ ((r & 7) << 2)) << 3)) = t;
                    }
                }
            }
            __syncthreads();
            // cooperative coalesced write: 8 warps x 8 rows
            #pragma unroll
            for (int i = 0; i < 8; ++i) {
                int r = i * 8 + wid;                 // local row 0..63
                int grow = (int)rowBase + half * 64 + r;
                if (grow < Nn) {
                    int u0 = (2 * lane) ^ ((r & 7) << 2);   // even unit -> 16B aligned
                    float4 hv = *reinterpret_cast<const float4*>(
                        smem + OFF_A + r * 512 + (u0 << 3));
                    *reinterpret_cast<float4*>(d_h + (size_t)grow * 128 + lane * 4) = hv;
                    if (writeNext) {
                        uint32_t h0, l0, h1, l1;
                        split_pack(hv.x, hv.y, h0, l0);
                        split_pack(hv.z, hv.w, h1, l1);
                        size_t off = (size_t)grow * 256 + 128 + lane * 4;
                        uint2 hh; hh.x = h0; hh.y = h1;
                        uint2 ll; ll.x = l0; ll.y = l1;
                        *reinterpret_cast<uint2*>(NAh + off) = hh;
                        *reinterpret_cast<uint2*>(NAl + off) = ll;
                    }
                }
            }
            __syncthreads();
        }
        // stage fully read before next tile's prefetch reuses OFF_A ✓
    }
}

// ============================================================================
// pooling: one graph per block, 256 threads (2-way row split halves latency chain)
// ============================================================================
__global__ __launch_bounds__(256) void pool_kernel() {
    __shared__ float s1[256], s2[256];
    int g = blockIdx.x;
    int c = threadIdx.x & 127, hf = threadIdx.x >> 7;
    int beg = d_gptr[g], end = d_gptr[g + 1];
    float mx = -3.402823466e38f, sm = 0.f;
    #pragma unroll 1
    for (int r = beg + hf; r < end; r += 2) {
        float v = d_h[(size_t)r * 128 + c];
        mx = fmaxf(mx, v);
        sm += v;
    }
    s1[threadIdx.x] = mx; s2[threadIdx.x] = sm;
    __syncthreads();
    if (hf == 0) {
        mx = fmaxf(mx, s1[c + 128]);
        sm += s2[c + 128];
        int cnt = end - beg;
        d_pooled[g * 256 + c]       = (cnt > 0) ? mx : 0.f;
        d_pooled[g * 256 + 128 + c] = sm / (float)(cnt > 1 ? cnt : 1);
    }
}

// head: out = pooled @ Wlin^T + blin  (R4-exact)
__global__ __launch_bounds__(256) void head_kernel(
    const float* __restrict__ Wlin, const float* __restrict__ blin,
    float* __restrict__ out)
{
    __shared__ float p[256];
    int g = blockIdx.x, o = threadIdx.x;
    p[o] = d_pooled[g * 256 + o];
    __syncthreads();
    float acc = blin[o];
    const float4* wr = reinterpret_cast<const float4*>(Wlin + o * 256);
    #pragma unroll 8
    for (int k = 0; k < 64; ++k) {
        float4 w = wr[k];
        float4 pv = *reinterpret_cast<const float4*>(&p[k * 4]);
        acc = fmaf(w.x, pv.x, acc);
        acc = fmaf(w.y, pv.y, acc);
        acc = fmaf(w.z, pv.z, acc);
        acc = fmaf(w.w, pv.w, acc);
    }
    out[g * 256 + o] = acc;
}

// ============================================================================
// launch — R4-exact sequence
// ============================================================================
extern "C" void kernel_launch(void* const* d_in, const int* in_sizes, int n_in,
                              void* d_out, int out_size)
{
    const float* x     = (const float*)d_in[0];
    const void*  ei    = d_in[1];
    const void*  batch = d_in[2];
    const float* W1l = (const float*)d_in[3];
    const float* b1  = (const float*)d_in[4];
    const float* W1r = (const float*)d_in[5];
    const float* W2l = (const float*)d_in[6];
    const float* b2  = (const float*)d_in[7];
    const float* W2r = (const float*)d_in[8];
    const float* W3l = (const float*)d_in[9];
    const float* b3  = (const float*)d_in[10];
    const float* W3r = (const float*)d_in[11];
    const float* Wlin = (const float*)d_in[12];
    const float* blin = (const float*)d_in[13];
    float* out = (float*)d_out;

    cudaFuncSetAttribute(sage_mma_gemm, cudaFuncAttributeMaxDynamicSharedMemorySize, GEMM_SMEM);

    detect_kernel<<<1, 1>>>(ei);
    gptr_kernel<<<1, 512>>>(batch);
    zero_kernel<<<98, 512>>>();
    deg_hist_kernel<<<512, 256>>>(ei);
    scan_kernel<<<1, 1024>>>();
    csr_fill_kernel<<<512, 256>>>(ei);

    wprep_kernel<<<384, 256>>>(W1l, W1r, W2l, W2r, W3l, W3r);
    xconv_kernel<<<6250, 256>>>(x);

    const int aggBlocks = (Nn * 32 + 255) / 256;   // warp per node

    // layer 1: reads A[1] (agg(x) | x), writes h1 + A[0] cols 128..255
    agg_kernel<<<aggBlocks, 256>>>(x, 1, 1);
    sage_mma_gemm<<<148, 256, GEMM_SMEM>>>(1, 0, 0, b1, 1, 1);
    // layer 2: reads A[0], writes h2 + A[1] cols 128..255
    agg_kernel<<<aggBlocks, 256>>>(nullptr, 0, 0);
    sage_mma_gemm<<<148, 256, GEMM_SMEM>>>(0, 1, 1, b2, 1, 1);
    // layer 3 (no relu) -> h3 only
    agg_kernel<<<aggBlocks, 256>>>(nullptr, 0, 1);
    sage_mma_gemm<<<148, 256, GEMM_SMEM>>>(1, 0, 2, b3, 0, 0);

    pool_kernel<<<Gg, 256>>>();
    head_kernel<<<Gg, 256>>>(Wlin, blin, out);
}

// round 8
// speedup vs baseline: 1.2972x; 1.0188x over previous
#include <cuda_runtime.h>
#include <cuda_bf16.h>
#include <cstdint>

#define Nn 50000
#define NnPad 50048
#define Ee 600000
#define Gg 512
#define NUM_TILES 391   // ceil(50000/128)

// ============================================================================
// PTX helpers: plain (non-'a') instructions only — ldmatrix / mma.sync / cp.async
// ============================================================================
__device__ __forceinline__ uint32_t smem_to_u32(const void* smem_ptr) {
    uint32_t addr;
    asm("{ .reg .u64 tmp; cvta.to.shared.u64 tmp, %1; cvt.u32.u64 %0, tmp; }"
        : "=r"(addr) : "l"(smem_ptr));
    return addr;
}

#define LDSM_X4(r0, r1, r2, r3, addr) \
    asm volatile("ldmatrix.sync.aligned.m8n8.x4.shared.b16 {%0,%1,%2,%3}, [%4];" \
        : "=r"(r0), "=r"(r1), "=r"(r2), "=r"(r3) : "r"(addr))

#define MMA16816(c, a0, a1, a2, a3, b0, b1) \
    asm volatile("mma.sync.aligned.m16n8k16.row.col.f32.bf16.bf16.f32 " \
        "{%0,%1,%2,%3}, {%4,%5,%6,%7}, {%8,%9}, {%0,%1,%2,%3};" \
        : "+f"((c)[0]), "+f"((c)[1]), "+f"((c)[2]), "+f"((c)[3]) \
        : "r"(a0), "r"(a1), "r"(a2), "r"(a3), "r"(b0), "r"(b1))

#define CP_ASYNC16(dst_u32, src_ptr) \
    asm volatile("cp.async.cg.shared.global [%0], [%1], 16;" \
        :: "r"(dst_u32), "l"(src_ptr) : "memory")
#define CP_COMMIT() asm volatile("cp.async.commit_group;" ::: "memory")
#define CP_WAIT1()  asm volatile("cp.async.wait_group 1;" ::: "memory")
#define CP_WAIT0()  asm volatile("cp.async.wait_group 0;" ::: "memory")

// ============================================================================
// Scratch (device globals: allocation-free)
// ============================================================================
__device__ __align__(16) __nv_bfloat16 d_Ahi[2][(size_t)NnPad * 256];
__device__ __align__(16) __nv_bfloat16 d_Alo[2][(size_t)NnPad * 256];
__device__ __align__(16) __nv_bfloat16 d_Wh[3 * 128 * 256];
__device__ __align__(16) __nv_bfloat16 d_Wl[3 * 128 * 256];
__device__ __align__(16) float d_h[(size_t)NnPad * 128];
__device__ float d_pooled[Gg * 256];
__device__ int   d_csr[Ee];
__device__ int   d_rowptr[Nn + 1];
__device__ int   d_cursor[Nn];
__device__ int   d_degi[Nn];
__device__ int   d_gptr[Gg + 1];
__device__ int   d_is64;

// ============================================================================
// index dtype handling (int64 vs int32)  — R4-exact
// ============================================================================
__device__ __forceinline__ int load_idx(const void* p, long long i, int is64) {
    if (is64) return (int)((const long long*)p)[i];
    return ((const int*)p)[i];
}
__global__ void detect_kernel(const void* __restrict__ ei) {
    const long long* p = (const long long*)ei;
    int ok = 1;
    for (int i = 0; i < 64; ++i) {
        long long v = p[i];
        if (v < 0 || v >= (long long)Nn) { ok = 0; break; }
    }
    d_is64 = ok;
}

__global__ void gptr_kernel(const void* __restrict__ batch) {
    int is64 = d_is64;
    int g = threadIdx.x;   // 0..511
    int lo = 0, hi = Nn;
    while (lo < hi) {
        int mid = (lo + hi) >> 1;
        int v = load_idx(batch, mid, is64);
        if (v < g) lo = mid + 1; else hi = mid;
    }
    d_gptr[g] = lo;
    if (g == 0) d_gptr[Gg] = Nn;
}

__global__ void zero_kernel() {
    int i = blockIdx.x * blockDim.x + threadIdx.x;
    int stride = gridDim.x * blockDim.x;
    for (int j = i; j < Nn; j += stride) { d_degi[j] = 0; d_cursor[j] = 0; }
}

__global__ void deg_hist_kernel(const void* __restrict__ ei) {
    int is64 = d_is64;
    int stride = gridDim.x * blockDim.x;
    for (int e = blockIdx.x * blockDim.x + threadIdx.x; e < Ee; e += stride) {
        int dst = load_idx(ei, (long long)Ee + e, is64);
        atomicAdd(&d_degi[dst], 1);
    }
}

// one-block exclusive scan: degi -> rowptr
__global__ void scan_kernel() {
    __shared__ int sh[1024];
    const int SEG = 49;   // 1024*49 = 50176 >= 50001
    int t = threadIdx.x;
    int base = t * SEG;
    int s = 0;
    #pragma unroll 7
    for (int i = 0; i < SEG; ++i) {
        int idx = base + i;
        if (idx < Nn) s += d_degi[idx];
    }
    sh[t] = s;
    __syncthreads();
    for (int off = 1; off < 1024; off <<= 1) {
        int v = (t >= off) ? sh[t - off] : 0;
        __syncthreads();
        sh[t] += v;
        __syncthreads();
    }
    int run = t ? sh[t - 1] : 0;
    #pragma unroll 7
    for (int i = 0; i < SEG; ++i) {
        int idx = base + i;
        if (idx < Nn) { d_rowptr[idx] = run; run += d_degi[idx]; }
        else if (idx == Nn) { d_rowptr[Nn] = run; }
    }
}

__global__ void csr_fill_kernel(const void* __restrict__ ei) {
    int is64 = d_is64;
    int stride = gridDim.x * blockDim.x;
    for (int e = blockIdx.x * blockDim.x + threadIdx.x; e < Ee; e += stride) {
        int src = load_idx(ei, e, is64);
        int dst = load_idx(ei, (long long)Ee + e, is64);
        int pos = d_rowptr[dst] + atomicAdd(&d_cursor[dst], 1);
        d_csr[pos] = src;
    }
}

// ============================================================================
// bf16 hi/lo split helpers
// ============================================================================
__device__ __forceinline__ void split_pack(float a, float b, uint32_t& hi, uint32_t& lo) {
    __nv_bfloat16 ha = __float2bfloat16_rn(a), hb = __float2bfloat16_rn(b);
    __nv_bfloat162 hv; hv.x = ha; hv.y = hb;
    hi = *reinterpret_cast<uint32_t*>(&hv);
    float la = a - __bfloat162float(ha);
    float lb = b - __bfloat162float(hb);
    __nv_bfloat162 lv = __floats2bfloat162_rn(la, lb);
    lo = *reinterpret_cast<uint32_t*>(&lv);
}

// convert weights: Wcat[layer][o][k] = k<128 ? Wl[o][k] : Wr[o][k-128], split hi/lo
__global__ void wprep_kernel(const float* W1l, const float* W1r,
                             const float* W2l, const float* W2r,
                             const float* W3l, const float* W3r) {
    int idx = blockIdx.x * blockDim.x + threadIdx.x;   // over 3*128*256
    if (idx >= 3 * 128 * 256) return;
    int layer = idx / (128 * 256);
    int rem = idx - layer * 128 * 256;
    int o = rem >> 8, k = rem & 255;
    const float* Wl = layer == 0 ? W1l : layer == 1 ? W2l : W3l;
    const float* Wr = layer == 0 ? W1r : layer == 1 ? W2r : W3r;
    float v = (k < 128) ? Wl[o * 128 + k] : Wr[o * 128 + k - 128];
    __nv_bfloat16 hv = __float2bfloat16_rn(v);
    float lvf = v - __bfloat162float(hv);
    d_Wh[idx] = hv;
    d_Wl[idx] = __float2bfloat16_rn(lvf);
}

// convert x into A buf[1], cols 128..255
__global__ void xconv_kernel(const float* __restrict__ x) {
    int idx = blockIdx.x * blockDim.x + threadIdx.x;   // Nn*32
    if (idx >= Nn * 32) return;
    int n = idx >> 5, c4 = idx & 31;
    float4 v = *reinterpret_cast<const float4*>(x + (size_t)n * 128 + c4 * 4);
    uint32_t h0, l0, h1, l1;
    split_pack(v.x, v.y, h0, l0);
    split_pack(v.z, v.w, h1, l1);
    size_t off = (size_t)n * 256 + 128 + c4 * 4;
    uint2 hh; hh.x = h0; hh.y = h1;
    uint2 ll; ll.x = l0; ll.y = l1;
    *reinterpret_cast<uint2*>(&d_Ahi[1][off]) = hh;
    *reinterpret_cast<uint2*>(&d_Alo[1][off]) = ll;
}

// ============================================================================
// mean aggregation: warp per node, cp.async-pipelined gather (MLP=4, ~20 regs)
//   Each lane cp.asyncs its own 16B of 4 neighbor rows into SMEM, waits, sums.
//   SMEM 16KB/CTA -> 8 CTAs/SM -> full 2048-thread occupancy preserved.
// ============================================================================
__global__ __launch_bounds__(256, 8) void agg_kernel(
    const float* __restrict__ x, int usex, int outsel)
{
    __shared__ __align__(16) char buf[8][4][512];
    const float* __restrict__ src = usex ? x : d_h;
    const int warp = (blockIdx.x * blockDim.x + threadIdx.x) >> 5;   // exactly Nn warps
    const int wl = threadIdx.x >> 5;
    const int lane = threadIdx.x & 31;
    const int beg = d_rowptr[warp];
    const int end = d_rowptr[warp + 1];
    const uint32_t sbase = smem_to_u32(&buf[wl][0][0]) + lane * 16;

    float4 acc = make_float4(0.f, 0.f, 0.f, 0.f);
    int e = beg;
    #pragma unroll 1
    while (e < end) {
        const int n = (end - e) < 4 ? (end - e) : 4;
        #pragma unroll
        for (int d = 0; d < 4; ++d) {
            if (d < n) {
                int s = d_csr[e + d];
                CP_ASYNC16(sbase + d * 512,
                           reinterpret_cast<const char*>(src + (size_t)s * 128) + lane * 16);
            }
        }
        CP_COMMIT();
        CP_WAIT0();
        // each lane reads exactly the 16B it issued — no cross-thread sync needed
        #pragma unroll
        for (int d = 0; d < 4; ++d) {
            if (d < n) {
                float4 v = *reinterpret_cast<const float4*>(&buf[wl][d][lane * 16]);
                acc.x += v.x; acc.y += v.y; acc.z += v.z; acc.w += v.w;
            }
        }
        e += n;
    }

    const int deg = end - beg;
    const float inv = 1.f / (float)(deg > 1 ? deg : 1);
    acc.x *= inv; acc.y *= inv; acc.z *= inv; acc.w *= inv;
    uint32_t h0, l0, h1, l1;
    split_pack(acc.x, acc.y, h0, l0);
    split_pack(acc.z, acc.w, h1, l1);
    size_t off = (size_t)warp * 256 + lane * 4;
    uint2 hh; hh.x = h0; hh.y = h1;
    uint2 ll; ll.x = l0; ll.y = l1;
    __nv_bfloat16* Ah = d_Ahi[outsel];
    __nv_bfloat16* Al = d_Alo[outsel];
    *reinterpret_cast<uint2*>(Ah + off) = hh;
    *reinterpret_cast<uint2*>(Al + off) = ll;
}

// ============================================================================
// Tensor-core GEMM via mma.sync (HMMA) — R4-exact (known-good 338us config)
// SMEM: Whi 64KB | Wlo 64KB | Abuf 2x16KB | bias 512B  = 164352 B
// ============================================================================
#define OFF_WHI  0
#define OFF_WLO  65536
#define OFF_A    131072
#define OFF_BIAS 163840
#define GEMM_SMEM 164352

__device__ __forceinline__ void prefetch_chunk(const __nv_bfloat16* __restrict__ src,
                                               size_t rowBase, int cbase,
                                               uint32_t dst, int tid) {
    #pragma unroll
    for (int j = 0; j < 4; ++j) {
        int u = tid + j * 256;          // 0..1023 16B units
        int r = u >> 3, uu = u & 7;
        const __nv_bfloat16* s = src + (rowBase + r) * 256 + cbase + uu * 8;
        uint32_t d = dst + r * 128 + (((uu ^ (r & 7))) << 4);
        CP_ASYNC16(d, s);
    }
}

__global__ __launch_bounds__(256, 1)
void sage_mma_gemm(int bufsel, int nextsel, int layer,
                   const float* __restrict__ bias, int do_relu, int writeNext)
{
    extern __shared__ char smem[];
    const uint32_t sb = smem_to_u32(smem);
    const int tid = threadIdx.x;
    const int wid = tid >> 5, lane = tid & 31;

    const __nv_bfloat16* __restrict__ Ahi = d_Ahi[bufsel];
    const __nv_bfloat16* __restrict__ Alo = d_Alo[bufsel];
    const __nv_bfloat16* __restrict__ WhiG = d_Wh + layer * 32768;
    const __nv_bfloat16* __restrict__ WloG = d_Wl + layer * 32768;
    __nv_bfloat16* __restrict__ NAh = d_Ahi[nextsel];
    __nv_bfloat16* __restrict__ NAl = d_Alo[nextsel];
    float* sbias = reinterpret_cast<float*>(smem + OFF_BIAS);

    // ---- load W (hi+lo) into swizzled SMEM: 4096 16B-units each ----
    #pragma unroll
    for (int m = 0; m < 2; ++m) {
        const __nv_bfloat16* srcW = m ? WloG : WhiG;
        char* dstW = smem + (m ? OFF_WLO : OFF_WHI);
        #pragma unroll 4
        for (int j = 0; j < 16; ++j) {
            int idx = tid + j * 256;     // 0..4095 16B units
            int n = idx >> 5, u = idx & 31;
            float4 v = *reinterpret_cast<const float4*>(srcW + n * 256 + u * 8);
            *reinterpret_cast<float4*>(dstW + n * 512 + ((u ^ (n & 7)) << 4)) = v;
        }
    }
    if (tid < 128) sbias[tid] = bias[tid];
    __syncthreads();

    const uint32_t sA  = sb + OFF_A;
    const int wrow = wid * 16;

    for (int tile = blockIdx.x; tile < NUM_TILES; tile += gridDim.x) {
        const size_t rowBase = (size_t)tile * 128;

        float acc[64];
        #pragma unroll
        for (int i = 0; i < 64; ++i) acc[i] = 0.f;

        // chunk c: matrix = (c&1)?Alo:Ahi, k-base = (c>>1)*64, buf = c&1
        prefetch_chunk(Ahi, rowBase, 0, sA, tid);
        CP_COMMIT();

        #pragma unroll 1
        for (int c = 0; c < 8; ++c) {
            if (c < 7) {
                int cn = c + 1;
                prefetch_chunk((cn & 1) ? Alo : Ahi, rowBase, (cn >> 1) * 64,
                               sA + (cn & 1) * 16384, tid);
                CP_COMMIT();
                CP_WAIT1();
            } else {
                CP_WAIT0();
            }
            __syncthreads();

            const uint32_t abuf = sA + (c & 1) * 16384;
            const int cbase = (c >> 1) * 64;
            const int nW = (c & 1) ? 1 : 2;   // hi chunk hits Whi+Wlo; lo chunk hits Whi

            #pragma unroll
            for (int ks = 0; ks < 4; ++ks) {
                uint32_t a0, a1, a2, a3;
                {
                    int r = wrow + (lane & 15);
                    int u = ks * 2 + (lane >> 4);
                    uint32_t ad = abuf + r * 128 + (((u ^ (r & 7))) << 4);
                    LDSM_X4(a0, a1, a2, a3, ad);
                }
                #pragma unroll
                for (int w2 = 0; w2 < 2; ++w2) {
                    if (w2 >= nW) break;
                    const uint32_t sW = sb + (w2 ? OFF_WLO : OFF_WHI);
                    #pragma unroll
                    for (int ntp = 0; ntp < 8; ++ntp) {
                        int n = ntp * 16 + (lane & 15);
                        int kg = cbase + ks * 16 + ((lane >> 4) << 3);
                        int u = kg >> 3;
                        uint32_t bd = sW + n * 512 + (((u ^ (n & 7))) << 4);
                        uint32_t b0, b1, b2, b3;
                        LDSM_X4(b0, b1, b2, b3, bd);
                        MMA16816(&acc[(ntp * 2 + 0) * 4], a0, a1, a2, a3, b0, b2);
                        MMA16816(&acc[(ntp * 2 + 1) * 4], a0, a1, a2, a3, b1, b3);
                    }
                }
            }
            __syncthreads();
        }

        // ---- epilogue: bias + relu, fp32 out + bf16 split for next layer ----
        const int g = lane >> 2, tg = lane & 3;
        const int r0g = (int)rowBase + wrow + g;
        #pragma unroll
        for (int nt = 0; nt < 16; ++nt) {
            int col = nt * 8 + tg * 2;
            float2 bb = *reinterpret_cast<const float2*>(&sbias[col]);
            float v0 = acc[nt * 4 + 0] + bb.x;
            float v1 = acc[nt * 4 + 1] + bb.y;
            float v2 = acc[nt * 4 + 2] + bb.x;
            float v3 = acc[nt * 4 + 3] + bb.y;
            if (do_relu) {
                v0 = fmaxf(v0, 0.f); v1 = fmaxf(v1, 0.f);
                v2 = fmaxf(v2, 0.f); v3 = fmaxf(v3, 0.f);
            }
            if (r0g < Nn) {
                float2 o; o.x = v0; o.y = v1;
                *reinterpret_cast<float2*>(d_h + (size_t)r0g * 128 + col) = o;
                if (writeNext) {
                    uint32_t hh, ll;
                    split_pack(v0, v1, hh, ll);
                    size_t off = (size_t)r0g * 256 + 128 + col;
                    *reinterpret_cast<uint32_t*>(NAh + off) = hh;
                    *reinterpret_cast<uint32_t*>(NAl + off) = ll;
                }
            }
            if (r0g + 8 < Nn) {
                float2 o; o.x = v2; o.y = v3;
                *reinterpret_cast<float2*>(d_h + (size_t)(r0g + 8) * 128 + col) = o;
                if (writeNext) {
                    uint32_t hh, ll;
                    split_pack(v2, v3, hh, ll);
                    size_t off = (size_t)(r0g + 8) * 256 + 128 + col;
                    *reinterpret_cast<uint32_t*>(NAh + off) = hh;
                    *reinterpret_cast<uint32_t*>(NAl + off) = ll;
                }
            }
        }
    }
}

// ============================================================================
// pooling + head — R4-exact
// ============================================================================
__global__ void pool_kernel() {
    int g = blockIdx.x;
    int c = threadIdx.x;              // 128 threads, one per column
    int beg = d_gptr[g], end = d_gptr[g + 1];
    float mx = -3.402823466e38f, sm = 0.f;
    for (int r = beg; r < end; ++r) {
        float v = d_h[(size_t)r * 128 + c];
        mx = fmaxf(mx, v);
        sm += v;
    }
    int cnt = end - beg;
    d_pooled[g * 256 + c]       = (cnt > 0) ? mx : 0.f;
    d_pooled[g * 256 + 128 + c] = sm / (float)(cnt > 1 ? cnt : 1);
}

__global__ __launch_bounds__(256) void head_kernel(
    const float* __restrict__ Wlin, const float* __restrict__ blin,
    float* __restrict__ out)
{
    __shared__ float p[256];
    int g = blockIdx.x, o = threadIdx.x;
    p[o] = d_pooled[g * 256 + o];
    __syncthreads();
    float acc = blin[o];
    const float4* wr = reinterpret_cast<const float4*>(Wlin + o * 256);
    #pragma unroll 8
    for (int k = 0; k < 64; ++k) {
        float4 w = wr[k];
        float4 pv = *reinterpret_cast<const float4*>(&p[k * 4]);
        acc = fmaf(w.x, pv.x, acc);
        acc = fmaf(w.y, pv.y, acc);
        acc = fmaf(w.z, pv.z, acc);
        acc = fmaf(w.w, pv.w, acc);
    }
    out[g * 256 + o] = acc;
}

// ============================================================================
// launch — R4-exact sequence
// ============================================================================
extern "C" void kernel_launch(void* const* d_in, const int* in_sizes, int n_in,
                              void* d_out, int out_size)
{
    const float* x     = (const float*)d_in[0];
    const void*  ei    = d_in[1];
    const void*  batch = d_in[2];
    const float* W1l = (const float*)d_in[3];
    const float* b1  = (const float*)d_in[4];
    const float* W1r = (const float*)d_in[5];
    const float* W2l = (const float*)d_in[6];
    const float* b2  = (const float*)d_in[7];
    const float* W2r = (const float*)d_in[8];
    const float* W3l = (const float*)d_in[9];
    const float* b3  = (const float*)d_in[10];
    const float* W3r = (const float*)d_in[11];
    const float* Wlin = (const float*)d_in[12];
    const float* blin = (const float*)d_in[13];
    float* out = (float*)d_out;

    cudaFuncSetAttribute(sage_mma_gemm, cudaFuncAttributeMaxDynamicSharedMemorySize, GEMM_SMEM);

    detect_kernel<<<1, 1>>>(ei);
    gptr_kernel<<<1, 512>>>(batch);
    zero_kernel<<<98, 512>>>();
    deg_hist_kernel<<<512, 256>>>(ei);
    scan_kernel<<<1, 1024>>>();
    csr_fill_kernel<<<512, 256>>>(ei);

    wprep_kernel<<<384, 256>>>(W1l, W1r, W2l, W2r, W3l, W3r);
    xconv_kernel<<<6250, 256>>>(x);

    const int aggBlocks = (Nn * 32 + 255) / 256;   // warp per node, exactly Nn warps

    // layer 1: reads A[1] (agg(x) | x), writes h1 + A[0] cols 128..255
    agg_kernel<<<aggBlocks, 256>>>(x, 1, 1);
    sage_mma_gemm<<<148, 256, GEMM_SMEM>>>(1, 0, 0, b1, 1, 1);
    // layer 2: reads A[0], writes h2 + A[1] cols 128..255
    agg_kernel<<<aggBlocks, 256>>>(nullptr, 0, 0);
    sage_mma_gemm<<<148, 256, GEMM_SMEM>>>(0, 1, 1, b2, 1, 1);
    // layer 3 (no relu) -> h3 only
    agg_kernel<<<aggBlocks, 256>>>(nullptr, 0, 1);
    sage_mma_gemm<<<148, 256, GEMM_SMEM>>>(1, 0, 2, b3, 0, 0);

    pool_kernel<<<Gg, 128>>>();
    head_kernel<<<Gg, 256>>>(Wlin, blin, out);
}

// round 9
// speedup vs baseline: 1.2990x; 1.0014x over previous
#include <cuda_runtime.h>
#include <cuda_bf16.h>
#include <cstdint>

#define Nn 50000
#define NnPad 50048
#define Ee 600000
#define Gg 512
#define NUM_TILES 391   // ceil(50000/128)

// ============================================================================
// PTX helpers: plain (non-'a') instructions only — ldmatrix / mma.sync / cp.async
// ============================================================================
__device__ __forceinline__ uint32_t smem_to_u32(const void* smem_ptr) {
    uint32_t addr;
    asm("{ .reg .u64 tmp; cvta.to.shared.u64 tmp, %1; cvt.u32.u64 %0, tmp; }"
        : "=r"(addr) : "l"(smem_ptr));
    return addr;
}

#define LDSM_X4(r0, r1, r2, r3, addr) \
    asm volatile("ldmatrix.sync.aligned.m8n8.x4.shared.b16 {%0,%1,%2,%3}, [%4];" \
        : "=r"(r0), "=r"(r1), "=r"(r2), "=r"(r3) : "r"(addr))

#define MMA16816(c, a0, a1, a2, a3, b0, b1) \
    asm volatile("mma.sync.aligned.m16n8k16.row.col.f32.bf16.bf16.f32 " \
        "{%0,%1,%2,%3}, {%4,%5,%6,%7}, {%8,%9}, {%0,%1,%2,%3};" \
        : "+f"((c)[0]), "+f"((c)[1]), "+f"((c)[2]), "+f"((c)[3]) \
        : "r"(a0), "r"(a1), "r"(a2), "r"(a3), "r"(b0), "r"(b1))

#define CP_ASYNC16(dst_u32, src_ptr) \
    asm volatile("cp.async.cg.shared.global [%0], [%1], 16;" \
        :: "r"(dst_u32), "l"(src_ptr) : "memory")
#define CP_COMMIT() asm volatile("cp.async.commit_group;" ::: "memory")
#define CP_WAIT1()  asm volatile("cp.async.wait_group 1;" ::: "memory")
#define CP_WAIT0()  asm volatile("cp.async.wait_group 0;" ::: "memory")

// ============================================================================
// Scratch (device globals: allocation-free)
// ============================================================================
__device__ __align__(16) __nv_bfloat16 d_Ahi[2][(size_t)NnPad * 256];
__device__ __align__(16) __nv_bfloat16 d_Alo[2][(size_t)NnPad * 256];
__device__ __align__(16) __nv_bfloat16 d_Wh[3 * 128 * 256];
__device__ __align__(16) __nv_bfloat16 d_Wl[3 * 128 * 256];
__device__ __align__(16) float d_h[(size_t)NnPad * 128];
__device__ float d_pooled[Gg * 256];
__device__ int   d_csr[Ee];
__device__ int   d_rowptr[Nn + 1];
__device__ int   d_cursor[Nn];
__device__ int   d_degi[Nn];
__device__ int   d_gptr[Gg + 1];
__device__ int   d_is64;

// ============================================================================
// index dtype handling (int64 vs int32)
// ============================================================================
__device__ __forceinline__ int load_idx(const void* p, long long i, int is64) {
    if (is64) return (int)((const long long*)p)[i];
    return ((const int*)p)[i];
}
__global__ void detect_kernel(const void* __restrict__ ei) {
    const long long* p = (const long long*)ei;
    int ok = 1;
    for (int i = 0; i < 64; ++i) {
        long long v = p[i];
        if (v < 0 || v >= (long long)Nn) { ok = 0; break; }
    }
    d_is64 = ok;
}

__global__ void gptr_kernel(const void* __restrict__ batch) {
    int is64 = d_is64;
    int g = threadIdx.x;   // 0..511
    int lo = 0, hi = Nn;
    while (lo < hi) {
        int mid = (lo + hi) >> 1;
        int v = load_idx(batch, mid, is64);
        if (v < g) lo = mid + 1; else hi = mid;
    }
    d_gptr[g] = lo;
    if (g == 0) d_gptr[Gg] = Nn;
}

__global__ void zero_kernel() {
    int i = blockIdx.x * blockDim.x + threadIdx.x;
    int stride = gridDim.x * blockDim.x;
    for (int j = i; j < Nn; j += stride) { d_degi[j] = 0; d_cursor[j] = 0; }
}

__global__ void deg_hist_kernel(const void* __restrict__ ei) {
    int is64 = d_is64;
    int stride = gridDim.x * blockDim.x;
    for (int e = blockIdx.x * blockDim.x + threadIdx.x; e < Ee; e += stride) {
        int dst = load_idx(ei, (long long)Ee + e, is64);
        atomicAdd(&d_degi[dst], 1);
    }
}

// one-block exclusive scan: degi -> rowptr
__global__ void scan_kernel() {
    __shared__ int sh[1024];
    const int SEG = 49;   // 1024*49 = 50176 >= 50001
    int t = threadIdx.x;
    int base = t * SEG;
    int s = 0;
    #pragma unroll 7
    for (int i = 0; i < SEG; ++i) {
        int idx = base + i;
        if (idx < Nn) s += d_degi[idx];
    }
    sh[t] = s;
    __syncthreads();
    for (int off = 1; off < 1024; off <<= 1) {
        int v = (t >= off) ? sh[t - off] : 0;
        __syncthreads();
        sh[t] += v;
        __syncthreads();
    }
    int run = t ? sh[t - 1] : 0;
    #pragma unroll 7
    for (int i = 0; i < SEG; ++i) {
        int idx = base + i;
        if (idx < Nn) { d_rowptr[idx] = run; run += d_degi[idx]; }
        else if (idx == Nn) { d_rowptr[Nn] = run; }
    }
}

__global__ void csr_fill_kernel(const void* __restrict__ ei) {
    int is64 = d_is64;
    int stride = gridDim.x * blockDim.x;
    for (int e = blockIdx.x * blockDim.x + threadIdx.x; e < Ee; e += stride) {
        int src = load_idx(ei, e, is64);
        int dst = load_idx(ei, (long long)Ee + e, is64);
        int pos = d_rowptr[dst] + atomicAdd(&d_cursor[dst], 1);
        d_csr[pos] = src;
    }
}

// ============================================================================
// bf16 hi/lo split helpers
// ============================================================================
__device__ __forceinline__ void split_pack(float a, float b, uint32_t& hi, uint32_t& lo) {
    __nv_bfloat16 ha = __float2bfloat16_rn(a), hb = __float2bfloat16_rn(b);
    __nv_bfloat162 hv; hv.x = ha; hv.y = hb;
    hi = *reinterpret_cast<uint32_t*>(&hv);
    float la = a - __bfloat162float(ha);
    float lb = b - __bfloat162float(hb);
    __nv_bfloat162 lv = __floats2bfloat162_rn(la, lb);
    lo = *reinterpret_cast<uint32_t*>(&lv);
}

// convert weights: Wcat[layer][o][k] = k<128 ? Wl[o][k] : Wr[o][k-128], split hi/lo
__global__ void wprep_kernel(const float* W1l, const float* W1r,
                             const float* W2l, const float* W2r,
                             const float* W3l, const float* W3r) {
    int idx = blockIdx.x * blockDim.x + threadIdx.x;   // over 3*128*256
    if (idx >= 3 * 128 * 256) return;
    int layer = idx / (128 * 256);
    int rem = idx - layer * 128 * 256;
    int o = rem >> 8, k = rem & 255;
    const float* Wl = layer == 0 ? W1l : layer == 1 ? W2l : W3l;
    const float* Wr = layer == 0 ? W1r : layer == 1 ? W2r : W3r;
    float v = (k < 128) ? Wl[o * 128 + k] : Wr[o * 128 + k - 128];
    __nv_bfloat16 hv = __float2bfloat16_rn(v);
    float lvf = v - __bfloat162float(hv);
    d_Wh[idx] = hv;
    d_Wl[idx] = __float2bfloat16_rn(lvf);
}

// convert x into A buf[1], cols 128..255
__global__ void xconv_kernel(const float* __restrict__ x) {
    int idx = blockIdx.x * blockDim.x + threadIdx.x;   // Nn*32
    if (idx >= Nn * 32) return;
    int n = idx >> 5, c4 = idx & 31;
    float4 v = *reinterpret_cast<const float4*>(x + (size_t)n * 128 + c4 * 4);
    uint32_t h0, l0, h1, l1;
    split_pack(v.x, v.y, h0, l0);
    split_pack(v.z, v.w, h1, l1);
    size_t off = (size_t)n * 256 + 128 + c4 * 4;
    uint2 hh; hh.x = h0; hh.y = h1;
    uint2 ll; ll.x = l0; ll.y = l1;
    *reinterpret_cast<uint2*>(&d_Ahi[1][off]) = hh;
    *reinterpret_cast<uint2*>(&d_Alo[1][off]) = ll;
}

// ============================================================================
// mean aggregation: warp per node, cp.async-pipelined gather (R8-exact)
// ============================================================================
__global__ __launch_bounds__(256, 8) void agg_kernel(
    const float* __restrict__ x, int usex, int outsel)
{
    __shared__ __align__(16) char buf[8][4][512];
    const float* __restrict__ src = usex ? x : d_h;
    const int warp = (blockIdx.x * blockDim.x + threadIdx.x) >> 5;   // exactly Nn warps
    const int wl = threadIdx.x >> 5;
    const int lane = threadIdx.x & 31;
    const int beg = d_rowptr[warp];
    const int end = d_rowptr[warp + 1];
    const uint32_t sbase = smem_to_u32(&buf[wl][0][0]) + lane * 16;

    float4 acc = make_float4(0.f, 0.f, 0.f, 0.f);
    int e = beg;
    #pragma unroll 1
    while (e < end) {
        const int n = (end - e) < 4 ? (end - e) : 4;
        #pragma unroll
        for (int d = 0; d < 4; ++d) {
            if (d < n) {
                int s = d_csr[e + d];
                CP_ASYNC16(sbase + d * 512,
                           reinterpret_cast<const char*>(src + (size_t)s * 128) + lane * 16);
            }
        }
        CP_COMMIT();
        CP_WAIT0();
        #pragma unroll
        for (int d = 0; d < 4; ++d) {
            if (d < n) {
                float4 v = *reinterpret_cast<const float4*>(&buf[wl][d][lane * 16]);
                acc.x += v.x; acc.y += v.y; acc.z += v.z; acc.w += v.w;
            }
        }
        e += n;
    }

    const int deg = end - beg;
    const float inv = 1.f / (float)(deg > 1 ? deg : 1);
    acc.x *= inv; acc.y *= inv; acc.z *= inv; acc.w *= inv;
    uint32_t h0, l0, h1, l1;
    split_pack(acc.x, acc.y, h0, l0);
    split_pack(acc.z, acc.w, h1, l1);
    size_t off = (size_t)warp * 256 + lane * 4;
    uint2 hh; hh.x = h0; hh.y = h1;
    uint2 ll; ll.x = l0; ll.y = l1;
    __nv_bfloat16* Ah = d_Ahi[outsel];
    __nv_bfloat16* Al = d_Alo[outsel];
    *reinterpret_cast<uint2*>(Ah + off) = hh;
    *reinterpret_cast<uint2*>(Al + off) = ll;
}

// ============================================================================
// Tensor-core GEMM via mma.sync (HMMA) — R4-exact (known-good 338us config)
// SMEM: Whi 64KB | Wlo 64KB | Abuf 2x16KB | bias 512B  = 164352 B
// ============================================================================
#define OFF_WHI  0
#define OFF_WLO  65536
#define OFF_A    131072
#define OFF_BIAS 163840
#define GEMM_SMEM 164352

__device__ __forceinline__ void prefetch_chunk(const __nv_bfloat16* __restrict__ src,
                                               size_t rowBase, int cbase,
                                               uint32_t dst, int tid) {
    #pragma unroll
    for (int j = 0; j < 4; ++j) {
        int u = tid + j * 256;          // 0..1023 16B units
        int r = u >> 3, uu = u & 7;
        const __nv_bfloat16* s = src + (rowBase + r) * 256 + cbase + uu * 8;
        uint32_t d = dst + r * 128 + (((uu ^ (r & 7))) << 4);
        CP_ASYNC16(d, s);
    }
}

__global__ __launch_bounds__(256, 1)
void sage_mma_gemm(int bufsel, int nextsel, int layer,
                   const float* __restrict__ bias, int do_relu, int writeNext)
{
    extern __shared__ char smem[];
    const uint32_t sb = smem_to_u32(smem);
    const int tid = threadIdx.x;
    const int wid = tid >> 5, lane = tid & 31;

    const __nv_bfloat16* __restrict__ Ahi = d_Ahi[bufsel];
    const __nv_bfloat16* __restrict__ Alo = d_Alo[bufsel];
    const __nv_bfloat16* __restrict__ WhiG = d_Wh + layer * 32768;
    const __nv_bfloat16* __restrict__ WloG = d_Wl + layer * 32768;
    __nv_bfloat16* __restrict__ NAh = d_Ahi[nextsel];
    __nv_bfloat16* __restrict__ NAl = d_Alo[nextsel];
    float* sbias = reinterpret_cast<float*>(smem + OFF_BIAS);

    // ---- load W (hi+lo) into swizzled SMEM: 4096 16B-units each ----
    #pragma unroll
    for (int m = 0; m < 2; ++m) {
        const __nv_bfloat16* srcW = m ? WloG : WhiG;
        char* dstW = smem + (m ? OFF_WLO : OFF_WHI);
        #pragma unroll 4
        for (int j = 0; j < 16; ++j) {
            int idx = tid + j * 256;     // 0..4095 16B units
            int n = idx >> 5, u = idx & 31;
            float4 v = *reinterpret_cast<const float4*>(srcW + n * 256 + u * 8);
            *reinterpret_cast<float4*>(dstW + n * 512 + ((u ^ (n & 7)) << 4)) = v;
        }
    }
    if (tid < 128) sbias[tid] = bias[tid];
    __syncthreads();

    const uint32_t sA  = sb + OFF_A;
    const int wrow = wid * 16;

    for (int tile = blockIdx.x; tile < NUM_TILES; tile += gridDim.x) {
        const size_t rowBase = (size_t)tile * 128;

        float acc[64];
        #pragma unroll
        for (int i = 0; i < 64; ++i) acc[i] = 0.f;

        // chunk c: matrix = (c&1)?Alo:Ahi, k-base = (c>>1)*64, buf = c&1
        prefetch_chunk(Ahi, rowBase, 0, sA, tid);
        CP_COMMIT();

        #pragma unroll 1
        for (int c = 0; c < 8; ++c) {
            if (c < 7) {
                int cn = c + 1;
                prefetch_chunk((cn & 1) ? Alo : Ahi, rowBase, (cn >> 1) * 64,
                               sA + (cn & 1) * 16384, tid);
                CP_COMMIT();
                CP_WAIT1();
            } else {
                CP_WAIT0();
            }
            __syncthreads();

            const uint32_t abuf = sA + (c & 1) * 16384;
            const int cbase = (c >> 1) * 64;
            const int nW = (c & 1) ? 1 : 2;   // hi chunk hits Whi+Wlo; lo chunk hits Whi

            #pragma unroll
            for (int ks = 0; ks < 4; ++ks) {
                uint32_t a0, a1, a2, a3;
                {
                    int r = wrow + (lane & 15);
                    int u = ks * 2 + (lane >> 4);
                    uint32_t ad = abuf + r * 128 + (((u ^ (r & 7))) << 4);
                    LDSM_X4(a0, a1, a2, a3, ad);
                }
                #pragma unroll
                for (int w2 = 0; w2 < 2; ++w2) {
                    if (w2 >= nW) break;
                    const uint32_t sW = sb + (w2 ? OFF_WLO : OFF_WHI);
                    #pragma unroll
                    for (int ntp = 0; ntp < 8; ++ntp) {
                        int n = ntp * 16 + (lane & 15);
                        int kg = cbase + ks * 16 + ((lane >> 4) << 3);
                        int u = kg >> 3;
                        uint32_t bd = sW + n * 512 + (((u ^ (n & 7))) << 4);
                        uint32_t b0, b1, b2, b3;
                        LDSM_X4(b0, b1, b2, b3, bd);
                        MMA16816(&acc[(ntp * 2 + 0) * 4], a0, a1, a2, a3, b0, b2);
                        MMA16816(&acc[(ntp * 2 + 1) * 4], a0, a1, a2, a3, b1, b3);
                    }
                }
            }
            __syncthreads();
        }

        // ---- epilogue: bias + relu, fp32 out + bf16 split for next layer ----
        const int g = lane >> 2, tg = lane & 3;
        const int r0g = (int)rowBase + wrow + g;
        #pragma unroll
        for (int nt = 0; nt < 16; ++nt) {
            int col = nt * 8 + tg * 2;
            float2 bb = *reinterpret_cast<const float2*>(&sbias[col]);
            float v0 = acc[nt * 4 + 0] + bb.x;
            float v1 = acc[nt * 4 + 1] + bb.y;
            float v2 = acc[nt * 4 + 2] + bb.x;
            float v3 = acc[nt * 4 + 3] + bb.y;
            if (do_relu) {
                v0 = fmaxf(v0, 0.f); v1 = fmaxf(v1, 0.f);
                v2 = fmaxf(v2, 0.f); v3 = fmaxf(v3, 0.f);
            }
            if (r0g < Nn) {
                float2 o; o.x = v0; o.y = v1;
                *reinterpret_cast<float2*>(d_h + (size_t)r0g * 128 + col) = o;
                if (writeNext) {
                    uint32_t hh, ll;
                    split_pack(v0, v1, hh, ll);
                    size_t off = (size_t)r0g * 256 + 128 + col;
                    *reinterpret_cast<uint32_t*>(NAh + off) = hh;
                    *reinterpret_cast<uint32_t*>(NAl + off) = ll;
                }
            }
            if (r0g + 8 < Nn) {
                float2 o; o.x = v2; o.y = v3;
                *reinterpret_cast<float2*>(d_h + (size_t)(r0g + 8) * 128 + col) = o;
                if (writeNext) {
                    uint32_t hh, ll;
                    split_pack(v2, v3, hh, ll);
                    size_t off = (size_t)(r0g + 8) * 256 + 128 + col;
                    *reinterpret_cast<uint32_t*>(NAh + off) = hh;
                    *reinterpret_cast<uint32_t*>(NAl + off) = ll;
                }
            }
        }
    }
}

// ============================================================================
// pooling + head — R4-exact
// ============================================================================
__global__ void pool_kernel() {
    int g = blockIdx.x;
    int c = threadIdx.x;              // 128 threads, one per column
    int beg = d_gptr[g], end = d_gptr[g + 1];
    float mx = -3.402823466e38f, sm = 0.f;
    for (int r = beg; r < end; ++r) {
        float v = d_h[(size_t)r * 128 + c];
        mx = fmaxf(mx, v);
        sm += v;
    }
    int cnt = end - beg;
    d_pooled[g * 256 + c]       = (cnt > 0) ? mx : 0.f;
    d_pooled[g * 256 + 128 + c] = sm / (float)(cnt > 1 ? cnt : 1);
}

__global__ __launch_bounds__(256) void head_kernel(
    const float* __restrict__ Wlin, const float* __restrict__ blin,
    float* __restrict__ out)
{
    __shared__ float p[256];
    int g = blockIdx.x, o = threadIdx.x;
    p[o] = d_pooled[g * 256 + o];
    __syncthreads();
    float acc = blin[o];
    const float4* wr = reinterpret_cast<const float4*>(Wlin + o * 256);
    #pragma unroll 8
    for (int k = 0; k < 64; ++k) {
        float4 w = wr[k];
        float4 pv = *reinterpret_cast<const float4*>(&p[k * 4]);
        acc = fmaf(w.x, pv.x, acc);
        acc = fmaf(w.y, pv.y, acc);
        acc = fmaf(w.z, pv.z, acc);
        acc = fmaf(w.w, pv.w, acc);
    }
    out[g * 256 + o] = acc;
}

// ============================================================================
// launch — forked-stream capture: wprep/xconv and gptr off the critical path
// ============================================================================
extern "C" void kernel_launch(void* const* d_in, const int* in_sizes, int n_in,
                              void* d_out, int out_size)
{
    const float* x     = (const float*)d_in[0];
    const void*  ei    = d_in[1];
    const void*  batch = d_in[2];
    const float* W1l = (const float*)d_in[3];
    const float* b1  = (const float*)d_in[4];
    const float* W1r = (const float*)d_in[5];
    const float* W2l = (const float*)d_in[6];
    const float* b2  = (const float*)d_in[7];
    const float* W2r = (const float*)d_in[8];
    const float* W3l = (const float*)d_in[9];
    const float* b3  = (const float*)d_in[10];
    const float* W3r = (const float*)d_in[11];
    const float* Wlin = (const float*)d_in[12];
    const float* blin = (const float*)d_in[13];
    float* out = (float*)d_out;

    cudaFuncSetAttribute(sage_mma_gemm, cudaFuncAttributeMaxDynamicSharedMemorySize, GEMM_SMEM);

    cudaStream_t s1, s2;
    cudaStreamCreateWithFlags(&s1, cudaStreamNonBlocking);
    cudaStreamCreateWithFlags(&s2, cudaStreamNonBlocking);
    cudaEvent_t evFork, evDet, evW, evG;
    cudaEventCreateWithFlags(&evFork, cudaEventDisableTiming);
    cudaEventCreateWithFlags(&evDet,  cudaEventDisableTiming);
    cudaEventCreateWithFlags(&evW,    cudaEventDisableTiming);
    cudaEventCreateWithFlags(&evG,    cudaEventDisableTiming);

    // ---- fork side branch 1: weight/x conversion (independent of edge data) ----
    cudaEventRecord(evFork, 0);
    cudaStreamWaitEvent(s1, evFork, 0);
    wprep_kernel<<<384, 256, 0, s1>>>(W1l, W1r, W2l, W2r, W3l, W3r);
    xconv_kernel<<<6250, 256, 0, s1>>>(x);
    cudaEventRecord(evW, s1);

    // ---- main chain: CSR build ----
    detect_kernel<<<1, 1>>>(ei);
    cudaEventRecord(evDet, 0);
    // side branch 2: gptr (needs detect only; consumed only by pool)
    cudaStreamWaitEvent(s2, evDet, 0);
    gptr_kernel<<<1, 512, 0, s2>>>(batch);
    cudaEventRecord(evG, s2);

    zero_kernel<<<98, 512>>>();
    deg_hist_kernel<<<512, 256>>>(ei);
    scan_kernel<<<1, 1024>>>();
    csr_fill_kernel<<<512, 256>>>(ei);

    const int aggBlocks = (Nn * 32 + 255) / 256;   // warp per node, exactly Nn warps

    // layer 1: agg(x) -> A[1] cols 0..127; gemm needs wprep+xconv (join s1)
    agg_kernel<<<aggBlocks, 256>>>(x, 1, 1);
    cudaStreamWaitEvent(0, evW, 0);
    sage_mma_gemm<<<148, 256, GEMM_SMEM>>>(1, 0, 0, b1, 1, 1);
    // layer 2
    agg_kernel<<<aggBlocks, 256>>>(nullptr, 0, 0);
    sage_mma_gemm<<<148, 256, GEMM_SMEM>>>(0, 1, 1, b2, 1, 1);
    // layer 3 (no relu)
    agg_kernel<<<aggBlocks, 256>>>(nullptr, 0, 1);
    sage_mma_gemm<<<148, 256, GEMM_SMEM>>>(1, 0, 2, b3, 0, 0);

    // pool needs gptr (join s2)
    cudaStreamWaitEvent(0, evG, 0);
    pool_kernel<<<Gg, 128>>>();
    head_kernel<<<Gg, 256>>>(Wlin, blin, out);

    cudaEventDestroy(evFork);
    cudaEventDestroy(evDet);
    cudaEventDestroy(evW);
    cudaEventDestroy(evG);
    cudaStreamDestroy(s1);
    cudaStreamDestroy(s2);
}